// round 1
// baseline (speedup 1.0000x reference)
#include <cuda_runtime.h>

// Problem constants (fixed by setup_inputs)
#define P_ATOMS 512
#define A_CH    4
#define K_DIM   49
#define N_DIM   8
#define NM      128
#define NM2     (NM*NM)
#define NM3     (NM*NM*NM)
#define G_PTS   1900
#define M_ROWS  (P_ATOMS*A_CH)   // 2048
#define KN_COLS (K_DIM*N_DIM)    // 392

// Scratch: F[(p*4+a)][g], row-major over g. 2048*1900*4B = 15.56 MB.
__device__ float g_F[M_ROWS * G_PTS];

// ---------------------------------------------------------------------------
// Kernel 1: B-spline interpolation -> F[(p,a)][g] = interp(p,g,a) * weights[g]
// One thread per (p,g). g fastest => coalesced F stores.
// ---------------------------------------------------------------------------
__global__ void __launch_bounds__(256)
interp_kernel(const float* __restrict__ pos,
              const float* __restrict__ mesh,
              const float* __restrict__ cell,
              const float* __restrict__ weights,
              const float* __restrict__ grid)
{
    int tid = blockIdx.x * blockDim.x + threadIdx.x;
    if (tid >= P_ATOMS * G_PTS) return;
    int p = tid / G_PTS;
    int g = tid - p * G_PTS;

    // 3x3 inverse of cell (cheap, all loads L1/L2-resident)
    float c00 = __ldg(cell+0), c01 = __ldg(cell+1), c02 = __ldg(cell+2);
    float c10 = __ldg(cell+3), c11 = __ldg(cell+4), c12 = __ldg(cell+5);
    float c20 = __ldg(cell+6), c21 = __ldg(cell+7), c22 = __ldg(cell+8);
    float m00 = c11*c22 - c12*c21;
    float m01 = c02*c21 - c01*c22;
    float m02 = c01*c12 - c02*c11;
    float m10 = c12*c20 - c10*c22;
    float m11 = c00*c22 - c02*c20;
    float m12 = c02*c10 - c00*c12;
    float m20 = c10*c21 - c11*c20;
    float m21 = c01*c20 - c00*c21;
    float m22 = c00*c11 - c01*c10;
    float rdet = 1.0f / (c00*m00 + c01*m10 + c02*m20);

    float px = __ldg(pos + p*3 + 0) + __ldg(grid + g*3 + 0);
    float py = __ldg(pos + p*3 + 1) + __ldg(grid + g*3 + 1);
    float pz = __ldg(pos + p*3 + 2) + __ldg(grid + g*3 + 2);

    // frac = point @ inv(cell)
    float fx = (px*m00 + py*m10 + pz*m20) * rdet;
    float fy = (px*m01 + py*m11 + pz*m21) * rdet;
    float fz = (px*m02 + py*m12 + pz*m22) * rdet;

    float wx[3], wy[3], wz[3];
    int ix[3], iy[3], iz[3];

    {
        float u  = fx * (float)NM;
        float nf = floorf(u + 0.5f);
        float x  = u - nf;
        wx[0] = 0.5f*(0.5f - x)*(0.5f - x);
        wx[1] = 0.75f - x*x;
        wx[2] = 0.5f*(0.5f + x)*(0.5f + x);
        int n = (int)nf;
        ix[0] = (n - 1 + 4*NM) % NM; ix[1] = (n + 4*NM) % NM; ix[2] = (n + 1 + 4*NM) % NM;
    }
    {
        float u  = fy * (float)NM;
        float nf = floorf(u + 0.5f);
        float x  = u - nf;
        wy[0] = 0.5f*(0.5f - x)*(0.5f - x);
        wy[1] = 0.75f - x*x;
        wy[2] = 0.5f*(0.5f + x)*(0.5f + x);
        int n = (int)nf;
        iy[0] = (n - 1 + 4*NM) % NM; iy[1] = (n + 4*NM) % NM; iy[2] = (n + 1 + 4*NM) % NM;
    }
    {
        float u  = fz * (float)NM;
        float nf = floorf(u + 0.5f);
        float x  = u - nf;
        wz[0] = 0.5f*(0.5f - x)*(0.5f - x);
        wz[1] = 0.75f - x*x;
        wz[2] = 0.5f*(0.5f + x)*(0.5f + x);
        int n = (int)nf;
        iz[0] = (n - 1 + 4*NM) % NM; iz[1] = (n + 4*NM) % NM; iz[2] = (n + 1 + 4*NM) % NM;
    }

    float acc0 = 0.f, acc1 = 0.f, acc2 = 0.f, acc3 = 0.f;
    #pragma unroll
    for (int dx = 0; dx < 3; ++dx) {
        int ox = ix[dx] * NM2;
        #pragma unroll
        for (int dy = 0; dy < 3; ++dy) {
            int oxy = ox + iy[dy] * NM;
            float wxy = wx[dx] * wy[dy];
            #pragma unroll
            for (int dz = 0; dz < 3; ++dz) {
                int off = oxy + iz[dz];
                float w = wxy * wz[dz];
                acc0 += w * __ldg(mesh + off);
                acc1 += w * __ldg(mesh + NM3   + off);
                acc2 += w * __ldg(mesh + 2*NM3 + off);
                acc3 += w * __ldg(mesh + 3*NM3 + off);
            }
        }
    }

    float wt = __ldg(weights + g);
    g_F[(p*A_CH + 0)*G_PTS + g] = acc0 * wt;
    g_F[(p*A_CH + 1)*G_PTS + g] = acc1 * wt;
    g_F[(p*A_CH + 2)*G_PTS + g] = acc2 * wt;
    g_F[(p*A_CH + 3)*G_PTS + g] = acc3 * wt;
}

// ---------------------------------------------------------------------------
// Kernel 2: NT GEMM  O[(p,a)][(k,n)] = sum_g F[(p,a)][g] * V[(k,n)][g]
// 64x64 tile, BK=16, 256 threads, 4x4 microtile. Epilogue permutes to pkan.
// ---------------------------------------------------------------------------
#define BM 64
#define BN 64
#define BK 16

__global__ void __launch_bounds__(256)
gemm_nt_kernel(const float* __restrict__ V, float* __restrict__ out)
{
    __shared__ float As[BK][BM + 1];
    __shared__ float Bs[BK][BN + 1];

    int tx = threadIdx.x & 15;   // 0..15 -> column group
    int ty = threadIdx.x >> 4;   // 0..15 -> row group
    int rowBase = blockIdx.y * BM;
    int colBase = blockIdx.x * BN;

    float acc[4][4];
    #pragma unroll
    for (int i = 0; i < 4; ++i)
        #pragma unroll
        for (int j = 0; j < 4; ++j) acc[i][j] = 0.f;

    for (int k0 = 0; k0 < G_PTS; k0 += BK) {
        // Load A tile (F): 64 rows x 16 k, coalesced over k within a row.
        #pragma unroll
        for (int i = 0; i < 4; ++i) {
            int e = threadIdx.x + i * 256;
            int r = e >> 4;
            int c = e & 15;
            int gk = k0 + c;
            float v = 0.f;
            if (gk < G_PTS)
                v = g_F[(rowBase + r) * G_PTS + gk];
            As[c][r] = v;
        }
        // Load B tile (V): 64 rows x 16 k, guard row < 392.
        #pragma unroll
        for (int i = 0; i < 4; ++i) {
            int e = threadIdx.x + i * 256;
            int r = e >> 4;
            int c = e & 15;
            int gk = k0 + c;
            int row = colBase + r;
            float v = 0.f;
            if (gk < G_PTS && row < KN_COLS)
                v = __ldg(V + row * G_PTS + gk);
            Bs[c][r] = v;
        }
        __syncthreads();

        #pragma unroll
        for (int kk = 0; kk < BK; ++kk) {
            float a0 = As[kk][ty*4 + 0];
            float a1 = As[kk][ty*4 + 1];
            float a2 = As[kk][ty*4 + 2];
            float a3 = As[kk][ty*4 + 3];
            float b0 = Bs[kk][tx*4 + 0];
            float b1 = Bs[kk][tx*4 + 1];
            float b2 = Bs[kk][tx*4 + 2];
            float b3 = Bs[kk][tx*4 + 3];
            acc[0][0] += a0*b0; acc[0][1] += a0*b1; acc[0][2] += a0*b2; acc[0][3] += a0*b3;
            acc[1][0] += a1*b0; acc[1][1] += a1*b1; acc[1][2] += a1*b2; acc[1][3] += a1*b3;
            acc[2][0] += a2*b0; acc[2][1] += a2*b1; acc[2][2] += a2*b2; acc[2][3] += a2*b3;
            acc[3][0] += a3*b0; acc[3][1] += a3*b1; acc[3][2] += a3*b2; acc[3][3] += a3*b3;
        }
        __syncthreads();
    }

    // Epilogue: row = p*4+a, col = k*8+n  ->  out[((p*49 + k)*4 + a)*8 + n]
    #pragma unroll
    for (int i = 0; i < 4; ++i) {
        int row = rowBase + ty*4 + i;
        int p = row >> 2;
        int a = row & 3;
        #pragma unroll
        for (int j = 0; j < 4; ++j) {
            int col = colBase + tx*4 + j;
            if (col < KN_COLS) {
                int k = col >> 3;   // /8
                int n = col & 7;    // %8
                out[((p*K_DIM + k)*A_CH + a)*N_DIM + n] = acc[i][j];
            }
        }
    }
}

// ---------------------------------------------------------------------------
extern "C" void kernel_launch(void* const* d_in, const int* in_sizes, int n_in,
                              void* d_out, int out_size) {
    const float* positions = (const float*)d_in[0];
    const float* mesh      = (const float*)d_in[1];
    const float* cell      = (const float*)d_in[2];
    const float* values    = (const float*)d_in[3];
    const float* weights   = (const float*)d_in[4];
    const float* grid      = (const float*)d_in[5];
    float* out = (float*)d_out;

    (void)in_sizes; (void)n_in; (void)out_size;

    int total = P_ATOMS * G_PTS;
    int blocks = (total + 255) / 256;
    interp_kernel<<<blocks, 256>>>(positions, mesh, cell, weights, grid);

    dim3 ggrid((KN_COLS + BN - 1) / BN, M_ROWS / BM);
    gemm_nt_kernel<<<ggrid, 256>>>(values, out);
}

// round 2
// speedup vs baseline: 2.1329x; 2.1329x over previous
#include <cuda_runtime.h>

// Problem constants (fixed by setup_inputs)
#define P_ATOMS 512
#define A_CH    4
#define K_DIM   49
#define N_DIM   8
#define NM      128
#define NM2     (NM*NM)
#define NM3     (NM*NM*NM)
#define G_PTS   1900          // 50 radial * 38 angular
#define N_RAD   50
#define N_ANG   38
#define M_ROWS  (P_ATOMS*A_CH)   // 2048
#define KN_COLS (K_DIM*N_DIM)    // 392

// ---------------------------------------------------------------------------
// Device scratch
// ---------------------------------------------------------------------------
__device__ float  g_F[M_ROWS * G_PTS];        // 15.6 MB  F[(p*4+a)][g2]
__device__ float4 g_meshT[NM3];               // 33.5 MB  meshT[x][y][z] = 4 channels
__device__ float  g_V2[KN_COLS * G_PTS];      // 3 MB     V2[(k*8+n)][g2]
__device__ float  g_w2[G_PTS];                // weights in g2 order
__device__ float4 g_grid2[G_PTS];             // grid points in g2 order (xyz, pad)

// g2 = ang*50 + r   <->   g = r*38 + ang
__device__ __forceinline__ int g_from_g2(int g2) {
    int ang = g2 / N_RAD;
    int r   = g2 - ang * N_RAD;
    return r * N_ANG + ang;
}

// ---------------------------------------------------------------------------
// Kernel A: transpose mesh [c][xyz] -> meshT[xyz][c] (float4)
// ---------------------------------------------------------------------------
__global__ void __launch_bounds__(256)
transpose_mesh_kernel(const float* __restrict__ mesh)
{
    int i = blockIdx.x * blockDim.x + threadIdx.x;
    if (i >= NM3) return;
    float4 v;
    v.x = __ldg(mesh + i);
    v.y = __ldg(mesh + NM3 + i);
    v.z = __ldg(mesh + 2*NM3 + i);
    v.w = __ldg(mesh + 3*NM3 + i);
    g_meshT[i] = v;
}

// ---------------------------------------------------------------------------
// Kernel B: permute values/weights/grid into g2 (radial-major) order
// ---------------------------------------------------------------------------
__global__ void __launch_bounds__(256)
permute_kernel(const float* __restrict__ values,
               const float* __restrict__ weights,
               const float* __restrict__ grid)
{
    int tid = blockIdx.x * blockDim.x + threadIdx.x;
    if (tid < KN_COLS * G_PTS) {
        int row = tid / G_PTS;
        int g2  = tid - row * G_PTS;
        g_V2[tid] = __ldg(values + row * G_PTS + g_from_g2(g2));
    }
    if (tid < G_PTS) {
        int g = g_from_g2(tid);
        g_w2[tid] = __ldg(weights + g);
        float4 gp;
        gp.x = __ldg(grid + g*3 + 0);
        gp.y = __ldg(grid + g*3 + 1);
        gp.z = __ldg(grid + g*3 + 2);
        gp.w = 0.f;
        g_grid2[tid] = gp;
    }
}

// ---------------------------------------------------------------------------
// Kernel C: interpolation.  thread -> (p, g2), lanes walk consecutive radial
// nodes along one ray => stencil addresses of adjacent lanes share sectors.
// One LDG.128 per stencil point gives all 4 channels.
// ---------------------------------------------------------------------------
__global__ void __launch_bounds__(256)
interp_kernel(const float* __restrict__ pos,
              const float* __restrict__ cell)
{
    int tid = blockIdx.x * blockDim.x + threadIdx.x;
    if (tid >= P_ATOMS * G_PTS) return;
    int p  = tid / G_PTS;
    int g2 = tid - p * G_PTS;

    // 3x3 inverse of cell
    float c00 = __ldg(cell+0), c01 = __ldg(cell+1), c02 = __ldg(cell+2);
    float c10 = __ldg(cell+3), c11 = __ldg(cell+4), c12 = __ldg(cell+5);
    float c20 = __ldg(cell+6), c21 = __ldg(cell+7), c22 = __ldg(cell+8);
    float m00 = c11*c22 - c12*c21;
    float m01 = c02*c21 - c01*c22;
    float m02 = c01*c12 - c02*c11;
    float m10 = c12*c20 - c10*c22;
    float m11 = c00*c22 - c02*c20;
    float m12 = c02*c10 - c00*c12;
    float m20 = c10*c21 - c11*c20;
    float m21 = c01*c20 - c00*c21;
    float m22 = c00*c11 - c01*c10;
    float rdet = 1.0f / (c00*m00 + c01*m10 + c02*m20);

    float4 gp = g_grid2[g2];
    float px = __ldg(pos + p*3 + 0) + gp.x;
    float py = __ldg(pos + p*3 + 1) + gp.y;
    float pz = __ldg(pos + p*3 + 2) + gp.z;

    float fx = (px*m00 + py*m10 + pz*m20) * rdet;
    float fy = (px*m01 + py*m11 + pz*m21) * rdet;
    float fz = (px*m02 + py*m12 + pz*m22) * rdet;

    float wx[3], wy[3], wz[3];
    int ix[3], iy[3], iz[3];
    {
        float u  = fx * (float)NM;
        float nf = floorf(u + 0.5f);
        float x  = u - nf;
        wx[0] = 0.5f*(0.5f - x)*(0.5f - x);
        wx[1] = 0.75f - x*x;
        wx[2] = 0.5f*(0.5f + x)*(0.5f + x);
        int n = (int)nf;
        ix[0] = (n - 1 + 4*NM) & (NM-1); ix[1] = (n + 4*NM) & (NM-1); ix[2] = (n + 1 + 4*NM) & (NM-1);
    }
    {
        float u  = fy * (float)NM;
        float nf = floorf(u + 0.5f);
        float x  = u - nf;
        wy[0] = 0.5f*(0.5f - x)*(0.5f - x);
        wy[1] = 0.75f - x*x;
        wy[2] = 0.5f*(0.5f + x)*(0.5f + x);
        int n = (int)nf;
        iy[0] = (n - 1 + 4*NM) & (NM-1); iy[1] = (n + 4*NM) & (NM-1); iy[2] = (n + 1 + 4*NM) & (NM-1);
    }
    {
        float u  = fz * (float)NM;
        float nf = floorf(u + 0.5f);
        float x  = u - nf;
        wz[0] = 0.5f*(0.5f - x)*(0.5f - x);
        wz[1] = 0.75f - x*x;
        wz[2] = 0.5f*(0.5f + x)*(0.5f + x);
        int n = (int)nf;
        iz[0] = (n - 1 + 4*NM) & (NM-1); iz[1] = (n + 4*NM) & (NM-1); iz[2] = (n + 1 + 4*NM) & (NM-1);
    }

    float acc0 = 0.f, acc1 = 0.f, acc2 = 0.f, acc3 = 0.f;
    #pragma unroll
    for (int dx = 0; dx < 3; ++dx) {
        int ox = ix[dx] * NM2;
        #pragma unroll
        for (int dy = 0; dy < 3; ++dy) {
            int oxy = ox + iy[dy] * NM;
            float wxy = wx[dx] * wy[dy];
            #pragma unroll
            for (int dz = 0; dz < 3; ++dz) {
                float w = wxy * wz[dz];
                float4 m = g_meshT[oxy + iz[dz]];
                acc0 += w * m.x;
                acc1 += w * m.y;
                acc2 += w * m.z;
                acc3 += w * m.w;
            }
        }
    }

    float wt = g_w2[g2];
    g_F[(p*A_CH + 0)*G_PTS + g2] = acc0 * wt;
    g_F[(p*A_CH + 1)*G_PTS + g2] = acc1 * wt;
    g_F[(p*A_CH + 2)*G_PTS + g2] = acc2 * wt;
    g_F[(p*A_CH + 3)*G_PTS + g2] = acc3 * wt;
}

// ---------------------------------------------------------------------------
// Kernel D: split-K NT GEMM.  O[(p,a)][(k,n)] += sum_g F*V2, atomicAdd epilogue
// ---------------------------------------------------------------------------
#define BM 64
#define BN 64
#define BK 16
#define KSPLIT 8
#define KCHUNK 240   // 15 * BK; 8*240 = 1920 >= 1900

__global__ void __launch_bounds__(256)
gemm_nt_kernel(float* __restrict__ out)
{
    __shared__ float As[BK][BM + 4];   // +4 keeps 16B alignment per row
    __shared__ float Bs[BK][BN + 4];

    int tx = threadIdx.x & 15;
    int ty = threadIdx.x >> 4;
    int rowBase = blockIdx.y * BM;
    int colBase = blockIdx.x * BN;
    int kstart  = blockIdx.z * KCHUNK;
    int kend    = kstart + KCHUNK;
    if (kend > G_PTS) kend = G_PTS;

    float acc[4][4];
    #pragma unroll
    for (int i = 0; i < 4; ++i)
        #pragma unroll
        for (int j = 0; j < 4; ++j) acc[i][j] = 0.f;

    for (int k0 = kstart; k0 < kend; k0 += BK) {
        #pragma unroll
        for (int i = 0; i < 4; ++i) {
            int e = threadIdx.x + i * 256;
            int r = e >> 4;
            int c = e & 15;
            int gk = k0 + c;
            As[c][r] = (gk < kend) ? g_F[(rowBase + r) * G_PTS + gk] : 0.f;
        }
        #pragma unroll
        for (int i = 0; i < 4; ++i) {
            int e = threadIdx.x + i * 256;
            int r = e >> 4;
            int c = e & 15;
            int gk = k0 + c;
            int row = colBase + r;
            float v = 0.f;
            if (gk < kend && row < KN_COLS)
                v = __ldg(g_V2 + row * G_PTS + gk);
            Bs[c][r] = v;
        }
        __syncthreads();

        #pragma unroll
        for (int kk = 0; kk < BK; ++kk) {
            float4 a = *reinterpret_cast<const float4*>(&As[kk][ty*4]);
            float4 b = *reinterpret_cast<const float4*>(&Bs[kk][tx*4]);
            acc[0][0] += a.x*b.x; acc[0][1] += a.x*b.y; acc[0][2] += a.x*b.z; acc[0][3] += a.x*b.w;
            acc[1][0] += a.y*b.x; acc[1][1] += a.y*b.y; acc[1][2] += a.y*b.z; acc[1][3] += a.y*b.w;
            acc[2][0] += a.z*b.x; acc[2][1] += a.z*b.y; acc[2][2] += a.z*b.z; acc[2][3] += a.z*b.w;
            acc[3][0] += a.w*b.x; acc[3][1] += a.w*b.y; acc[3][2] += a.w*b.z; acc[3][3] += a.w*b.w;
        }
        __syncthreads();
    }

    // Epilogue: row = p*4+a, col = k*8+n  ->  out[((p*49 + k)*4 + a)*8 + n]
    #pragma unroll
    for (int i = 0; i < 4; ++i) {
        int row = rowBase + ty*4 + i;
        int p = row >> 2;
        int a = row & 3;
        #pragma unroll
        for (int j = 0; j < 4; ++j) {
            int col = colBase + tx*4 + j;
            if (col < KN_COLS) {
                int k = col >> 3;
                int n = col & 7;
                atomicAdd(out + ((p*K_DIM + k)*A_CH + a)*N_DIM + n, acc[i][j]);
            }
        }
    }
}

// ---------------------------------------------------------------------------
extern "C" void kernel_launch(void* const* d_in, const int* in_sizes, int n_in,
                              void* d_out, int out_size) {
    const float* positions = (const float*)d_in[0];
    const float* mesh      = (const float*)d_in[1];
    const float* cell      = (const float*)d_in[2];
    const float* values    = (const float*)d_in[3];
    const float* weights   = (const float*)d_in[4];
    const float* grid      = (const float*)d_in[5];
    float* out = (float*)d_out;
    (void)in_sizes; (void)n_in;

    transpose_mesh_kernel<<<(NM3 + 255) / 256, 256>>>(mesh);
    permute_kernel<<<(KN_COLS * G_PTS + 255) / 256, 256>>>(values, weights, grid);

    int total = P_ATOMS * G_PTS;
    interp_kernel<<<(total + 255) / 256, 256>>>(positions, cell);

    cudaMemsetAsync(out, 0, (size_t)out_size * sizeof(float));

    dim3 ggrid((KN_COLS + BN - 1) / BN, M_ROWS / BM, KSPLIT);
    gemm_nt_kernel<<<ggrid, 256>>>(out);
}

// round 4
// speedup vs baseline: 3.1569x; 1.4801x over previous
#include <cuda_runtime.h>
#include <cstdint>

// ---------------------------------------------------------------------------
// Problem constants
// ---------------------------------------------------------------------------
#define P_ATOMS 512
#define A_CH    4
#define K_DIM   49
#define N_DIM   8
#define NM      128
#define NM2     (NM*NM)
#define NM3     (NM*NM*NM)
#define G_PTS   1900
#define G_PAD   1920            // padded K (pad cols stay zero-init)
#define N_RAD   50
#define N_ANG   38
#define M_ROWS  (P_ATOMS*A_CH)  // 2048
#define KN_COLS (K_DIM*N_DIM)   // 392
#define KN_PAD  448             // padded N for GEMM tiles (7 * 64)

#define KSPLIT  4
#define KCHUNK  480             // 4*480 = 1920
#define BM      128
#define BN      64
#define BK      16
#define NIT     (KCHUNK/BK)     // 30

// ---------------------------------------------------------------------------
// Device scratch (zero-initialized at module load; pads never written)
// ---------------------------------------------------------------------------
__device__ float  g_F[M_ROWS * G_PAD];           // 15.7 MB  F[(p*4+a)][g2] (tf32-rounded)
__device__ float  g_V2[KN_PAD * G_PAD];          // 3.4 MB   V2[(k*8+n)][g2] (tf32-rounded)
__device__ float4 g_meshT[NM3];                  // 33.5 MB  channel-last mesh
__device__ float  g_w2[G_PTS];
__device__ float4 g_grid2[G_PTS];
__device__ float  g_part[KSPLIT * M_ROWS * KN_PAD];  // 14.7 MB split-K partials

// ---------------------------------------------------------------------------
// helpers
// ---------------------------------------------------------------------------
__device__ __forceinline__ float to_tf32(float x) {
    uint32_t u;
    asm("cvt.rna.tf32.f32 %0, %1;" : "=r"(u) : "f"(x));
    return __uint_as_float(u);
}

#define CP_ASYNC16(dst, src) \
    asm volatile("cp.async.cg.shared.global [%0], [%1], 16;" :: "r"(dst), "l"(src) : "memory")
#define CP_COMMIT() asm volatile("cp.async.commit_group;" ::: "memory")
#define CP_WAIT(n)  asm volatile("cp.async.wait_group %0;" :: "n"(n) : "memory")

#define MMA_TF32(c, a, b) \
    asm volatile("mma.sync.aligned.m16n8k8.row.col.f32.tf32.tf32.f32 " \
        "{%0,%1,%2,%3}, {%4,%5,%6,%7}, {%8,%9}, {%0,%1,%2,%3};" \
        : "+f"((c)[0]), "+f"((c)[1]), "+f"((c)[2]), "+f"((c)[3]) \
        : "r"((a)[0]), "r"((a)[1]), "r"((a)[2]), "r"((a)[3]), \
          "r"((b)[0]), "r"((b)[1]))

// g2 = ang*50 + r   <->   g = r*38 + ang
__device__ __forceinline__ int g_from_g2(int g2) {
    int ang = g2 / N_RAD;
    int r   = g2 - ang * N_RAD;
    return r * N_ANG + ang;
}

// ---------------------------------------------------------------------------
// Kernel A: mesh transpose to channel-last float4
// ---------------------------------------------------------------------------
__global__ void __launch_bounds__(256)
transpose_mesh_kernel(const float* __restrict__ mesh) {
    int i = blockIdx.x * blockDim.x + threadIdx.x;
    if (i >= NM3) return;
    float4 v;
    v.x = __ldg(mesh + i);
    v.y = __ldg(mesh + NM3 + i);
    v.z = __ldg(mesh + 2*NM3 + i);
    v.w = __ldg(mesh + 3*NM3 + i);
    g_meshT[i] = v;
}

// ---------------------------------------------------------------------------
// Kernel B: permute values/weights/grid into g2 order; V2 rounded to tf32
// ---------------------------------------------------------------------------
__global__ void __launch_bounds__(256)
permute_kernel(const float* __restrict__ values,
               const float* __restrict__ weights,
               const float* __restrict__ grid) {
    int tid = blockIdx.x * blockDim.x + threadIdx.x;
    if (tid < KN_COLS * G_PTS) {
        int row = tid / G_PTS;
        int g2  = tid - row * G_PTS;
        g_V2[row * G_PAD + g2] = to_tf32(__ldg(values + row * G_PTS + g_from_g2(g2)));
    }
    if (tid < G_PTS) {
        int g = g_from_g2(tid);
        g_w2[tid] = __ldg(weights + g);
        float4 gp;
        gp.x = __ldg(grid + g*3 + 0);
        gp.y = __ldg(grid + g*3 + 1);
        gp.z = __ldg(grid + g*3 + 2);
        gp.w = 0.f;
        g_grid2[tid] = gp;
    }
}

// ---------------------------------------------------------------------------
// Kernel C: B-spline interpolation -> tf32-rounded F[(p,a)][g2]
// ---------------------------------------------------------------------------
__global__ void __launch_bounds__(256)
interp_kernel(const float* __restrict__ pos, const float* __restrict__ cell) {
    int tid = blockIdx.x * blockDim.x + threadIdx.x;
    if (tid >= P_ATOMS * G_PTS) return;
    int p  = tid / G_PTS;
    int g2 = tid - p * G_PTS;

    float c00 = __ldg(cell+0), c01 = __ldg(cell+1), c02 = __ldg(cell+2);
    float c10 = __ldg(cell+3), c11 = __ldg(cell+4), c12 = __ldg(cell+5);
    float c20 = __ldg(cell+6), c21 = __ldg(cell+7), c22 = __ldg(cell+8);
    float m00 = c11*c22 - c12*c21;
    float m01 = c02*c21 - c01*c22;
    float m02 = c01*c12 - c02*c11;
    float m10 = c12*c20 - c10*c22;
    float m11 = c00*c22 - c02*c20;
    float m12 = c02*c10 - c00*c12;
    float m20 = c10*c21 - c11*c20;
    float m21 = c01*c20 - c00*c21;
    float m22 = c00*c11 - c01*c10;
    float rdet = 1.0f / (c00*m00 + c01*m10 + c02*m20);

    float4 gp = g_grid2[g2];
    float px = __ldg(pos + p*3 + 0) + gp.x;
    float py = __ldg(pos + p*3 + 1) + gp.y;
    float pz = __ldg(pos + p*3 + 2) + gp.z;

    float fx = (px*m00 + py*m10 + pz*m20) * rdet;
    float fy = (px*m01 + py*m11 + pz*m21) * rdet;
    float fz = (px*m02 + py*m12 + pz*m22) * rdet;

    float wx[3], wy[3], wz[3];
    int ix[3], iy[3], iz[3];
    {
        float u = fx * (float)NM, nf = floorf(u + 0.5f), x = u - nf;
        wx[0] = 0.5f*(0.5f-x)*(0.5f-x); wx[1] = 0.75f - x*x; wx[2] = 0.5f*(0.5f+x)*(0.5f+x);
        int n = (int)nf;
        ix[0] = (n-1+4*NM)&(NM-1); ix[1] = (n+4*NM)&(NM-1); ix[2] = (n+1+4*NM)&(NM-1);
    }
    {
        float u = fy * (float)NM, nf = floorf(u + 0.5f), x = u - nf;
        wy[0] = 0.5f*(0.5f-x)*(0.5f-x); wy[1] = 0.75f - x*x; wy[2] = 0.5f*(0.5f+x)*(0.5f+x);
        int n = (int)nf;
        iy[0] = (n-1+4*NM)&(NM-1); iy[1] = (n+4*NM)&(NM-1); iy[2] = (n+1+4*NM)&(NM-1);
    }
    {
        float u = fz * (float)NM, nf = floorf(u + 0.5f), x = u - nf;
        wz[0] = 0.5f*(0.5f-x)*(0.5f-x); wz[1] = 0.75f - x*x; wz[2] = 0.5f*(0.5f+x)*(0.5f+x);
        int n = (int)nf;
        iz[0] = (n-1+4*NM)&(NM-1); iz[1] = (n+4*NM)&(NM-1); iz[2] = (n+1+4*NM)&(NM-1);
    }

    float acc0 = 0.f, acc1 = 0.f, acc2 = 0.f, acc3 = 0.f;
    #pragma unroll
    for (int dx = 0; dx < 3; ++dx) {
        int ox = ix[dx] * NM2;
        #pragma unroll
        for (int dy = 0; dy < 3; ++dy) {
            int oxy = ox + iy[dy] * NM;
            float wxy = wx[dx] * wy[dy];
            #pragma unroll
            for (int dz = 0; dz < 3; ++dz) {
                float w = wxy * wz[dz];
                float4 m = g_meshT[oxy + iz[dz]];
                acc0 += w * m.x; acc1 += w * m.y; acc2 += w * m.z; acc3 += w * m.w;
            }
        }
    }

    float wt = g_w2[g2];
    g_F[(p*A_CH + 0)*G_PAD + g2] = to_tf32(acc0 * wt);
    g_F[(p*A_CH + 1)*G_PAD + g2] = to_tf32(acc1 * wt);
    g_F[(p*A_CH + 2)*G_PAD + g2] = to_tf32(acc2 * wt);
    g_F[(p*A_CH + 3)*G_PAD + g2] = to_tf32(acc3 * wt);
}

// ---------------------------------------------------------------------------
// Kernel D: tf32 mma.sync GEMM.  C[m][kn] = sum_g F[m][g] * V2[kn][g]
// Block 128x64, BK=16, 8 warps (warp tile 32x32 = 2x4 m16n8k8), split-K 4,
// cp.async double buffer. Partials to g_part (no atomics).
// ---------------------------------------------------------------------------
__global__ void __launch_bounds__(256, 1)
gemm_mma_kernel() {
    __shared__ float As[2][BM][BK + 4];   // 2*128*20*4 = 20480 B
    __shared__ float Bs[2][BN][BK + 4];   // 2* 64*20*4 = 10240 B

    const int tid  = threadIdx.x;
    const int lane = tid & 31;
    const int wid  = tid >> 5;
    const int warpM = wid & 3;    // 4 warps over M (32 rows each)
    const int warpN = wid >> 2;   // 2 warps over N (32 cols each)
    const int gRow = lane >> 2;   // 0..7
    const int gCol = lane & 3;    // 0..3

    const int n0    = blockIdx.x * BN;     // 0..384
    const int m0    = blockIdx.y * BM;     // 0..1920
    const int bz    = blockIdx.z;
    const int kbase = bz * KCHUNK;

    // smem u32 base addresses for cp.async
    uint32_t asBase = (uint32_t)__cvta_generic_to_shared(&As[0][0][0]);
    uint32_t bsBase = (uint32_t)__cvta_generic_to_shared(&Bs[0][0][0]);
    const uint32_t A_STAGE = BM * (BK + 4) * 4;
    const uint32_t B_STAGE = BN * (BK + 4) * 4;

    // stage loader: A = 512 cp16 (2/thread), B = 256 cp16 (1/thread)
    auto load_stage = [&](int it, int buf) {
        int kofs = kbase + it * BK;
        #pragma unroll
        for (int i = 0; i < 2; ++i) {
            int e   = tid + i * 256;
            int row = e >> 2;
            int c4  = e & 3;
            uint32_t dst = asBase + buf * A_STAGE + (row * (BK + 4) + c4 * 4) * 4;
            const float* src = g_F + (size_t)(m0 + row) * G_PAD + kofs + c4 * 4;
            CP_ASYNC16(dst, src);
        }
        {
            int row = tid >> 2;
            int c4  = tid & 3;
            uint32_t dst = bsBase + buf * B_STAGE + (row * (BK + 4) + c4 * 4) * 4;
            const float* src = g_V2 + (size_t)(n0 + row) * G_PAD + kofs + c4 * 4;
            CP_ASYNC16(dst, src);
        }
        CP_COMMIT();
    };

    float c[2][4][4];
    #pragma unroll
    for (int mt = 0; mt < 2; ++mt)
        #pragma unroll
        for (int nt = 0; nt < 4; ++nt)
            #pragma unroll
            for (int j = 0; j < 4; ++j) c[mt][nt][j] = 0.f;

    load_stage(0, 0);

    for (int it = 0; it < NIT; ++it) {
        int buf = it & 1;
        if (it + 1 < NIT) { load_stage(it + 1, buf ^ 1); CP_WAIT(1); }
        else              { CP_WAIT(0); }
        __syncthreads();

        #pragma unroll
        for (int ks = 0; ks < 2; ++ks) {
            uint32_t a[2][4], b[4][2];
            #pragma unroll
            for (int mt = 0; mt < 2; ++mt) {
                int r = warpM * 32 + mt * 16 + gRow;
                a[mt][0] = __float_as_uint(As[buf][r    ][ks*8     + gCol]);
                a[mt][1] = __float_as_uint(As[buf][r + 8][ks*8     + gCol]);
                a[mt][2] = __float_as_uint(As[buf][r    ][ks*8 + 4 + gCol]);
                a[mt][3] = __float_as_uint(As[buf][r + 8][ks*8 + 4 + gCol]);
            }
            #pragma unroll
            for (int nt = 0; nt < 4; ++nt) {
                int rb = warpN * 32 + nt * 8 + gRow;
                b[nt][0] = __float_as_uint(Bs[buf][rb][ks*8     + gCol]);
                b[nt][1] = __float_as_uint(Bs[buf][rb][ks*8 + 4 + gCol]);
            }
            #pragma unroll
            for (int mt = 0; mt < 2; ++mt)
                #pragma unroll
                for (int nt = 0; nt < 4; ++nt)
                    MMA_TF32(c[mt][nt], a[mt], b[nt]);
        }
        __syncthreads();
    }

    // epilogue: partials, float2 stores
    #pragma unroll
    for (int mt = 0; mt < 2; ++mt) {
        int row = m0 + warpM * 32 + mt * 16 + gRow;
        #pragma unroll
        for (int nt = 0; nt < 4; ++nt) {
            int col = n0 + warpN * 32 + nt * 8 + gCol * 2;
            float* base0 = g_part + ((size_t)bz * M_ROWS + row)     * KN_PAD + col;
            float* base1 = g_part + ((size_t)bz * M_ROWS + row + 8) * KN_PAD + col;
            *reinterpret_cast<float2*>(base0) = make_float2(c[mt][nt][0], c[mt][nt][1]);
            *reinterpret_cast<float2*>(base1) = make_float2(c[mt][nt][2], c[mt][nt][3]);
        }
    }
}

// ---------------------------------------------------------------------------
// Kernel E: split-K reduce + pkan permutation (coalesced out writes)
// ---------------------------------------------------------------------------
__global__ void __launch_bounds__(256)
reduce_kernel(float* __restrict__ out) {
    int idx = blockIdx.x * blockDim.x + threadIdx.x;   // = out linear index
    if (idx >= M_ROWS * KN_COLS) return;
    // out layout: ((p*49 + k)*4 + a)*8 + n
    int n   = idx & 7;
    int a   = (idx >> 3) & 3;
    int rem = idx >> 5;
    int k   = rem % K_DIM;
    int p   = rem / K_DIM;
    int m   = p * A_CH + a;
    int kn  = k * N_DIM + n;
    size_t o = (size_t)m * KN_PAD + kn;
    float s = g_part[o]
            + g_part[(size_t)1 * M_ROWS * KN_PAD + o]
            + g_part[(size_t)2 * M_ROWS * KN_PAD + o]
            + g_part[(size_t)3 * M_ROWS * KN_PAD + o];
    out[idx] = s;
}

// ---------------------------------------------------------------------------
extern "C" void kernel_launch(void* const* d_in, const int* in_sizes, int n_in,
                              void* d_out, int out_size) {
    const float* positions = (const float*)d_in[0];
    const float* mesh      = (const float*)d_in[1];
    const float* cell      = (const float*)d_in[2];
    const float* values    = (const float*)d_in[3];
    const float* weights   = (const float*)d_in[4];
    const float* grid      = (const float*)d_in[5];
    float* out = (float*)d_out;
    (void)in_sizes; (void)n_in; (void)out_size;

    transpose_mesh_kernel<<<(NM3 + 255) / 256, 256>>>(mesh);
    permute_kernel<<<(KN_COLS * G_PTS + 255) / 256, 256>>>(values, weights, grid);
    interp_kernel<<<(P_ATOMS * G_PTS + 255) / 256, 256>>>(positions, cell);

    dim3 ggrid(KN_PAD / BN, M_ROWS / BM, KSPLIT);   // (7, 16, 4)
    gemm_mma_kernel<<<ggrid, 256>>>();

    reduce_kernel<<<(M_ROWS * KN_COLS + 255) / 256, 256>>>(out);
}

// round 5
// speedup vs baseline: 3.2756x; 1.0376x over previous
#include <cuda_runtime.h>
#include <cstdint>

// ---------------------------------------------------------------------------
// Problem constants
// ---------------------------------------------------------------------------
#define P_ATOMS 512
#define A_CH    4
#define K_DIM   49
#define N_DIM   8
#define NM      128
#define NM2     (NM*NM)
#define NM3     (NM*NM*NM)
#define G_PTS   1900
#define G_PAD   1920            // padded K (pad cols stay zero-init)
#define N_RAD   50
#define N_ANG   38
#define M_ROWS  (P_ATOMS*A_CH)  // 2048
#define KN_COLS (K_DIM*N_DIM)   // 392
#define KN_PAD  448             // padded N for GEMM tiles (7 * 64)

#define KSPLIT  8
#define KCHUNK  240             // 8*240 = 1920
#define BM      128
#define BN      64
#define BK      16
#define NIT     (KCHUNK/BK)     // 15

// ---------------------------------------------------------------------------
// Device scratch (zero-initialized at module load; pads never written)
// ---------------------------------------------------------------------------
__device__ float  g_F[M_ROWS * G_PAD];               // 15.7 MB
__device__ float  g_V2[KN_PAD * G_PAD];              // 3.4 MB
__device__ float4 g_meshT[NM3];                      // 33.5 MB
__device__ float  g_w2[G_PTS];
__device__ float4 g_grid2[G_PTS];
__device__ float  g_part[KSPLIT * M_ROWS * KN_PAD];  // 29.4 MB

// ---------------------------------------------------------------------------
// helpers
// ---------------------------------------------------------------------------
__device__ __forceinline__ float to_tf32(float x) {
    uint32_t u;
    asm("cvt.rna.tf32.f32 %0, %1;" : "=r"(u) : "f"(x));
    return __uint_as_float(u);
}

#define CP_ASYNC16(dst, src) \
    asm volatile("cp.async.cg.shared.global [%0], [%1], 16;" :: "r"(dst), "l"(src) : "memory")
#define CP_COMMIT() asm volatile("cp.async.commit_group;" ::: "memory")
#define CP_WAIT(n)  asm volatile("cp.async.wait_group %0;" :: "n"(n) : "memory")

#define MMA_TF32(c, a, b) \
    asm volatile("mma.sync.aligned.m16n8k8.row.col.f32.tf32.tf32.f32 " \
        "{%0,%1,%2,%3}, {%4,%5,%6,%7}, {%8,%9}, {%0,%1,%2,%3};" \
        : "+f"((c)[0]), "+f"((c)[1]), "+f"((c)[2]), "+f"((c)[3]) \
        : "r"((a)[0]), "r"((a)[1]), "r"((a)[2]), "r"((a)[3]), \
          "r"((b)[0]), "r"((b)[1]))

// g2 = ang*50 + r   <->   g = r*38 + ang
__device__ __forceinline__ int g_from_g2(int g2) {
    int ang = g2 / N_RAD;
    int r   = g2 - ang * N_RAD;
    return r * N_ANG + ang;
}

// ---------------------------------------------------------------------------
// Kernel A: prep — mesh transpose to channel-last float4 AND g2-permutation
// of values/weights/grid (merged to save a launch)
// ---------------------------------------------------------------------------
__global__ void __launch_bounds__(256)
prep_kernel(const float* __restrict__ mesh,
            const float* __restrict__ values,
            const float* __restrict__ weights,
            const float* __restrict__ grid) {
    int i = blockIdx.x * blockDim.x + threadIdx.x;
    if (i < NM3) {
        float4 v;
        v.x = __ldg(mesh + i);
        v.y = __ldg(mesh + NM3 + i);
        v.z = __ldg(mesh + 2*NM3 + i);
        v.w = __ldg(mesh + 3*NM3 + i);
        g_meshT[i] = v;
    }
    if (i < KN_COLS * G_PTS) {
        int row = i / G_PTS;
        int g2  = i - row * G_PTS;
        g_V2[row * G_PAD + g2] = to_tf32(__ldg(values + row * G_PTS + g_from_g2(g2)));
    }
    if (i < G_PTS) {
        int g = g_from_g2(i);
        g_w2[i] = __ldg(weights + g);
        float4 gp;
        gp.x = __ldg(grid + g*3 + 0);
        gp.y = __ldg(grid + g*3 + 1);
        gp.z = __ldg(grid + g*3 + 2);
        gp.w = 0.f;
        g_grid2[i] = gp;
    }
}

// ---------------------------------------------------------------------------
// Kernel B: B-spline interpolation -> tf32-rounded F[(p,a)][g2]
// ---------------------------------------------------------------------------
__global__ void __launch_bounds__(256)
interp_kernel(const float* __restrict__ pos, const float* __restrict__ cell) {
    int tid = blockIdx.x * blockDim.x + threadIdx.x;
    if (tid >= P_ATOMS * G_PTS) return;
    int p  = tid / G_PTS;
    int g2 = tid - p * G_PTS;

    float c00 = __ldg(cell+0), c01 = __ldg(cell+1), c02 = __ldg(cell+2);
    float c10 = __ldg(cell+3), c11 = __ldg(cell+4), c12 = __ldg(cell+5);
    float c20 = __ldg(cell+6), c21 = __ldg(cell+7), c22 = __ldg(cell+8);
    float m00 = c11*c22 - c12*c21;
    float m01 = c02*c21 - c01*c22;
    float m02 = c01*c12 - c02*c11;
    float m10 = c12*c20 - c10*c22;
    float m11 = c00*c22 - c02*c20;
    float m12 = c02*c10 - c00*c12;
    float m20 = c10*c21 - c11*c20;
    float m21 = c01*c20 - c00*c21;
    float m22 = c00*c11 - c01*c10;
    float rdet = 1.0f / (c00*m00 + c01*m10 + c02*m20);

    float4 gp = g_grid2[g2];
    float px = __ldg(pos + p*3 + 0) + gp.x;
    float py = __ldg(pos + p*3 + 1) + gp.y;
    float pz = __ldg(pos + p*3 + 2) + gp.z;

    float fx = (px*m00 + py*m10 + pz*m20) * rdet;
    float fy = (px*m01 + py*m11 + pz*m21) * rdet;
    float fz = (px*m02 + py*m12 + pz*m22) * rdet;

    float wx[3], wy[3], wz[3];
    int ix[3], iy[3], iz[3];
    {
        float u = fx * (float)NM, nf = floorf(u + 0.5f), x = u - nf;
        wx[0] = 0.5f*(0.5f-x)*(0.5f-x); wx[1] = 0.75f - x*x; wx[2] = 0.5f*(0.5f+x)*(0.5f+x);
        int n = (int)nf;
        ix[0] = (n-1+4*NM)&(NM-1); ix[1] = (n+4*NM)&(NM-1); ix[2] = (n+1+4*NM)&(NM-1);
    }
    {
        float u = fy * (float)NM, nf = floorf(u + 0.5f), x = u - nf;
        wy[0] = 0.5f*(0.5f-x)*(0.5f-x); wy[1] = 0.75f - x*x; wy[2] = 0.5f*(0.5f+x)*(0.5f+x);
        int n = (int)nf;
        iy[0] = (n-1+4*NM)&(NM-1); iy[1] = (n+4*NM)&(NM-1); iy[2] = (n+1+4*NM)&(NM-1);
    }
    {
        float u = fz * (float)NM, nf = floorf(u + 0.5f), x = u - nf;
        wz[0] = 0.5f*(0.5f-x)*(0.5f-x); wz[1] = 0.75f - x*x; wz[2] = 0.5f*(0.5f+x)*(0.5f+x);
        int n = (int)nf;
        iz[0] = (n-1+4*NM)&(NM-1); iz[1] = (n+4*NM)&(NM-1); iz[2] = (n+1+4*NM)&(NM-1);
    }

    float acc0 = 0.f, acc1 = 0.f, acc2 = 0.f, acc3 = 0.f;
    #pragma unroll
    for (int dx = 0; dx < 3; ++dx) {
        int ox = ix[dx] * NM2;
        #pragma unroll
        for (int dy = 0; dy < 3; ++dy) {
            int oxy = ox + iy[dy] * NM;
            float wxy = wx[dx] * wy[dy];
            #pragma unroll
            for (int dz = 0; dz < 3; ++dz) {
                float w = wxy * wz[dz];
                float4 m = g_meshT[oxy + iz[dz]];
                acc0 += w * m.x; acc1 += w * m.y; acc2 += w * m.z; acc3 += w * m.w;
            }
        }
    }

    float wt = g_w2[g2];
    g_F[(p*A_CH + 0)*G_PAD + g2] = to_tf32(acc0 * wt);
    g_F[(p*A_CH + 1)*G_PAD + g2] = to_tf32(acc1 * wt);
    g_F[(p*A_CH + 2)*G_PAD + g2] = to_tf32(acc2 * wt);
    g_F[(p*A_CH + 3)*G_PAD + g2] = to_tf32(acc3 * wt);
}

// ---------------------------------------------------------------------------
// Kernel C: tf32 mma.sync GEMM.  C[m][kn] = sum_g F[m][g] * V2[kn][g]
// Block 128x64, BK=16, 8 warps (warp tile 32x32 = 2x4 m16n8k8), split-K 8,
// 3-stage cp.async ring, single __syncthreads per iteration.
// ---------------------------------------------------------------------------
__global__ void __launch_bounds__(256, 1)
gemm_mma_kernel() {
    __shared__ float As[3][BM][BK + 4];   // 3*128*20*4 = 30720 B
    __shared__ float Bs[3][BN][BK + 4];   // 3* 64*20*4 = 15360 B  (total 46080)

    const int tid  = threadIdx.x;
    const int lane = tid & 31;
    const int wid  = tid >> 5;
    const int warpM = wid & 3;    // 4 warps over M (32 rows each)
    const int warpN = wid >> 2;   // 2 warps over N (32 cols each)
    const int gRow = lane >> 2;   // 0..7
    const int gCol = lane & 3;    // 0..3

    const int n0    = blockIdx.x * BN;     // 0..384
    const int m0    = blockIdx.y * BM;     // 0..1920
    const int bz    = blockIdx.z;
    const int kbase = bz * KCHUNK;

    uint32_t asBase = (uint32_t)__cvta_generic_to_shared(&As[0][0][0]);
    uint32_t bsBase = (uint32_t)__cvta_generic_to_shared(&Bs[0][0][0]);
    const uint32_t A_STAGE = BM * (BK + 4) * 4;
    const uint32_t B_STAGE = BN * (BK + 4) * 4;

    // one stage: A = 512 cp16 (2/thread), B = 256 cp16 (1/thread)
    auto load_stage = [&](int it, int buf) {
        int kofs = kbase + it * BK;
        #pragma unroll
        for (int i = 0; i < 2; ++i) {
            int e   = tid + i * 256;
            int row = e >> 2;
            int c4  = e & 3;
            uint32_t dst = asBase + buf * A_STAGE + (row * (BK + 4) + c4 * 4) * 4;
            const float* src = g_F + (size_t)(m0 + row) * G_PAD + kofs + c4 * 4;
            CP_ASYNC16(dst, src);
        }
        {
            int row = tid >> 2;
            int c4  = tid & 3;
            uint32_t dst = bsBase + buf * B_STAGE + (row * (BK + 4) + c4 * 4) * 4;
            const float* src = g_V2 + (size_t)(n0 + row) * G_PAD + kofs + c4 * 4;
            CP_ASYNC16(dst, src);
        }
        CP_COMMIT();
    };

    float c[2][4][4];
    #pragma unroll
    for (int mt = 0; mt < 2; ++mt)
        #pragma unroll
        for (int nt = 0; nt < 4; ++nt)
            #pragma unroll
            for (int j = 0; j < 4; ++j) c[mt][nt][j] = 0.f;

    load_stage(0, 0);
    load_stage(1, 1);

    #pragma unroll 1
    for (int it = 0; it < NIT; ++it) {
        int buf = it % 3;
        if (it == NIT - 1) { CP_WAIT(0); } else { CP_WAIT(1); }
        __syncthreads();
        if (it + 2 < NIT) load_stage(it + 2, (it + 2) % 3);

        #pragma unroll
        for (int ks = 0; ks < 2; ++ks) {
            uint32_t a[2][4], b[4][2];
            #pragma unroll
            for (int mt = 0; mt < 2; ++mt) {
                int r = warpM * 32 + mt * 16 + gRow;
                a[mt][0] = __float_as_uint(As[buf][r    ][ks*8     + gCol]);
                a[mt][1] = __float_as_uint(As[buf][r + 8][ks*8     + gCol]);
                a[mt][2] = __float_as_uint(As[buf][r    ][ks*8 + 4 + gCol]);
                a[mt][3] = __float_as_uint(As[buf][r + 8][ks*8 + 4 + gCol]);
            }
            #pragma unroll
            for (int nt = 0; nt < 4; ++nt) {
                int rb = warpN * 32 + nt * 8 + gRow;
                b[nt][0] = __float_as_uint(Bs[buf][rb][ks*8     + gCol]);
                b[nt][1] = __float_as_uint(Bs[buf][rb][ks*8 + 4 + gCol]);
            }
            #pragma unroll
            for (int mt = 0; mt < 2; ++mt)
                #pragma unroll
                for (int nt = 0; nt < 4; ++nt)
                    MMA_TF32(c[mt][nt], a[mt], b[nt]);
        }
    }

    // epilogue: partials, float2 stores
    #pragma unroll
    for (int mt = 0; mt < 2; ++mt) {
        int row = m0 + warpM * 32 + mt * 16 + gRow;
        #pragma unroll
        for (int nt = 0; nt < 4; ++nt) {
            int col = n0 + warpN * 32 + nt * 8 + gCol * 2;
            float* base0 = g_part + ((size_t)bz * M_ROWS + row)     * KN_PAD + col;
            float* base1 = g_part + ((size_t)bz * M_ROWS + row + 8) * KN_PAD + col;
            *reinterpret_cast<float2*>(base0) = make_float2(c[mt][nt][0], c[mt][nt][1]);
            *reinterpret_cast<float2*>(base1) = make_float2(c[mt][nt][2], c[mt][nt][3]);
        }
    }
}

// ---------------------------------------------------------------------------
// Kernel D: split-K reduce + pkan permutation (coalesced out writes)
// ---------------------------------------------------------------------------
__global__ void __launch_bounds__(256)
reduce_kernel(float* __restrict__ out) {
    int idx = blockIdx.x * blockDim.x + threadIdx.x;   // = out linear index
    if (idx >= M_ROWS * KN_COLS) return;
    // out layout: ((p*49 + k)*4 + a)*8 + n
    int n   = idx & 7;
    int a   = (idx >> 3) & 3;
    int rem = idx >> 5;
    int k   = rem % K_DIM;
    int p   = rem / K_DIM;
    int m   = p * A_CH + a;
    int kn  = k * N_DIM + n;
    size_t o = (size_t)m * KN_PAD + kn;
    float s = 0.f;
    #pragma unroll
    for (int z = 0; z < KSPLIT; ++z)
        s += g_part[(size_t)z * M_ROWS * KN_PAD + o];
    out[idx] = s;
}

// ---------------------------------------------------------------------------
extern "C" void kernel_launch(void* const* d_in, const int* in_sizes, int n_in,
                              void* d_out, int out_size) {
    const float* positions = (const float*)d_in[0];
    const float* mesh      = (const float*)d_in[1];
    const float* cell      = (const float*)d_in[2];
    const float* values    = (const float*)d_in[3];
    const float* weights   = (const float*)d_in[4];
    const float* grid      = (const float*)d_in[5];
    float* out = (float*)d_out;
    (void)in_sizes; (void)n_in; (void)out_size;

    prep_kernel<<<(NM3 + 255) / 256, 256>>>(mesh, values, weights, grid);
    interp_kernel<<<(P_ATOMS * G_PTS + 255) / 256, 256>>>(positions, cell);

    dim3 ggrid(KN_PAD / BN, M_ROWS / BM, KSPLIT);   // (7, 16, 8)
    gemm_mma_kernel<<<ggrid, 256>>>();

    reduce_kernel<<<(M_ROWS * KN_COLS + 255) / 256, 256>>>(out);
}

// round 6
// speedup vs baseline: 3.4638x; 1.0575x over previous
#include <cuda_runtime.h>
#include <cstdint>

// ---------------------------------------------------------------------------
// Problem constants
// ---------------------------------------------------------------------------
#define P_ATOMS 512
#define A_CH    4
#define K_DIM   49
#define N_DIM   8
#define NM      128
#define NM2     (NM*NM)
#define NM3     (NM*NM*NM)
#define G_PTS   1900
#define G_PAD   1920            // padded K (pad cols stay zero-init)
#define N_RAD   50
#define N_ANG   38
#define M_ROWS  (P_ATOMS*A_CH)  // 2048
#define KN_COLS (K_DIM*N_DIM)   // 392
#define KN_PAD  448             // padded N for GEMM tiles (7 * 64)

#define KSPLIT  4
#define KCHUNK  480             // 4*480 = 1920
#define BM      128
#define BN      64
#define BK      32
#define NIT     (KCHUNK/BK)     // 15
#define BKP     (BK + 4)        // padded row stride (36 floats)

// dynamic smem layout: A stages then B stages
#define A_STAGE_F (BM * BKP)            // 4608 floats
#define B_STAGE_F (BN * BKP)            // 2304 floats
#define SMEM_FLOATS (3 * (A_STAGE_F + B_STAGE_F))
#define SMEM_BYTES  (SMEM_FLOATS * 4)   // 82944 B

// ---------------------------------------------------------------------------
// Device scratch (zero-initialized at module load; pads never written)
// ---------------------------------------------------------------------------
__device__ float  g_F[M_ROWS * G_PAD];               // 15.7 MB
__device__ float  g_V2[KN_PAD * G_PAD];              // 3.4 MB
__device__ float4 g_meshT[NM3];                      // 33.5 MB
__device__ float  g_w2[G_PTS];
__device__ float4 g_grid2[G_PTS];
__device__ float  g_part[KSPLIT * M_ROWS * KN_PAD];  // 14.7 MB
__device__ float  g_inv[9];                          // inverse cell (prep)

// ---------------------------------------------------------------------------
// helpers
// ---------------------------------------------------------------------------
__device__ __forceinline__ float to_tf32(float x) {
    uint32_t u;
    asm("cvt.rna.tf32.f32 %0, %1;" : "=r"(u) : "f"(x));
    return __uint_as_float(u);
}

#define CP_ASYNC16(dst, src) \
    asm volatile("cp.async.cg.shared.global [%0], [%1], 16;" :: "r"(dst), "l"(src) : "memory")
#define CP_COMMIT() asm volatile("cp.async.commit_group;" ::: "memory")
#define CP_WAIT(n)  asm volatile("cp.async.wait_group %0;" :: "n"(n) : "memory")

#define MMA_TF32(c, a, b) \
    asm volatile("mma.sync.aligned.m16n8k8.row.col.f32.tf32.tf32.f32 " \
        "{%0,%1,%2,%3}, {%4,%5,%6,%7}, {%8,%9}, {%0,%1,%2,%3};" \
        : "+f"((c)[0]), "+f"((c)[1]), "+f"((c)[2]), "+f"((c)[3]) \
        : "r"((a)[0]), "r"((a)[1]), "r"((a)[2]), "r"((a)[3]), \
          "r"((b)[0]), "r"((b)[1]))

// g2 = ang*50 + r   <->   g = r*38 + ang
__device__ __forceinline__ int g_from_g2(int g2) {
    int ang = g2 / N_RAD;
    int r   = g2 - ang * N_RAD;
    return r * N_ANG + ang;
}

// ---------------------------------------------------------------------------
// Kernel A: prep — mesh transpose, g2-permutation, cell inverse
// ---------------------------------------------------------------------------
__global__ void __launch_bounds__(256)
prep_kernel(const float* __restrict__ mesh,
            const float* __restrict__ values,
            const float* __restrict__ weights,
            const float* __restrict__ grid,
            const float* __restrict__ cell) {
    int i = blockIdx.x * blockDim.x + threadIdx.x;
    if (i < NM3) {
        float4 v;
        v.x = __ldg(mesh + i);
        v.y = __ldg(mesh + NM3 + i);
        v.z = __ldg(mesh + 2*NM3 + i);
        v.w = __ldg(mesh + 3*NM3 + i);
        g_meshT[i] = v;
    }
    if (i < KN_COLS * G_PTS) {
        int row = i / G_PTS;
        int g2  = i - row * G_PTS;
        g_V2[row * G_PAD + g2] = to_tf32(__ldg(values + row * G_PTS + g_from_g2(g2)));
    }
    if (i < G_PTS) {
        int g = g_from_g2(i);
        g_w2[i] = __ldg(weights + g);
        float4 gp;
        gp.x = __ldg(grid + g*3 + 0);
        gp.y = __ldg(grid + g*3 + 1);
        gp.z = __ldg(grid + g*3 + 2);
        gp.w = 0.f;
        g_grid2[i] = gp;
    }
    if (i == 0) {
        float c00 = cell[0], c01 = cell[1], c02 = cell[2];
        float c10 = cell[3], c11 = cell[4], c12 = cell[5];
        float c20 = cell[6], c21 = cell[7], c22 = cell[8];
        float m00 = c11*c22 - c12*c21;
        float m01 = c02*c21 - c01*c22;
        float m02 = c01*c12 - c02*c11;
        float m10 = c12*c20 - c10*c22;
        float m11 = c00*c22 - c02*c20;
        float m12 = c02*c10 - c00*c12;
        float m20 = c10*c21 - c11*c20;
        float m21 = c01*c20 - c00*c21;
        float m22 = c00*c11 - c01*c10;
        float rdet = 1.0f / (c00*m00 + c01*m10 + c02*m20);
        g_inv[0] = m00*rdet; g_inv[1] = m01*rdet; g_inv[2] = m02*rdet;
        g_inv[3] = m10*rdet; g_inv[4] = m11*rdet; g_inv[5] = m12*rdet;
        g_inv[6] = m20*rdet; g_inv[7] = m21*rdet; g_inv[8] = m22*rdet;
    }
}

// ---------------------------------------------------------------------------
// Kernel B: B-spline interpolation -> tf32-rounded F[(p,a)][g2]
// ---------------------------------------------------------------------------
__global__ void __launch_bounds__(256)
interp_kernel(const float* __restrict__ pos) {
    int tid = blockIdx.x * blockDim.x + threadIdx.x;
    if (tid >= P_ATOMS * G_PTS) return;
    int p  = tid / G_PTS;
    int g2 = tid - p * G_PTS;

    float m00 = g_inv[0], m01 = g_inv[1], m02 = g_inv[2];
    float m10 = g_inv[3], m11 = g_inv[4], m12 = g_inv[5];
    float m20 = g_inv[6], m21 = g_inv[7], m22 = g_inv[8];

    float4 gp = g_grid2[g2];
    float px = __ldg(pos + p*3 + 0) + gp.x;
    float py = __ldg(pos + p*3 + 1) + gp.y;
    float pz = __ldg(pos + p*3 + 2) + gp.z;

    float fx = px*m00 + py*m10 + pz*m20;
    float fy = px*m01 + py*m11 + pz*m21;
    float fz = px*m02 + py*m12 + pz*m22;

    float wx[3], wy[3], wz[3];
    int ix[3], iy[3], iz[3];
    {
        float u = fx * (float)NM, nf = floorf(u + 0.5f), x = u - nf;
        wx[0] = 0.5f*(0.5f-x)*(0.5f-x); wx[1] = 0.75f - x*x; wx[2] = 0.5f*(0.5f+x)*(0.5f+x);
        int n = (int)nf;
        ix[0] = (n-1+4*NM)&(NM-1); ix[1] = (n+4*NM)&(NM-1); ix[2] = (n+1+4*NM)&(NM-1);
    }
    {
        float u = fy * (float)NM, nf = floorf(u + 0.5f), x = u - nf;
        wy[0] = 0.5f*(0.5f-x)*(0.5f-x); wy[1] = 0.75f - x*x; wy[2] = 0.5f*(0.5f+x)*(0.5f+x);
        int n = (int)nf;
        iy[0] = (n-1+4*NM)&(NM-1); iy[1] = (n+4*NM)&(NM-1); iy[2] = (n+1+4*NM)&(NM-1);
    }
    {
        float u = fz * (float)NM, nf = floorf(u + 0.5f), x = u - nf;
        wz[0] = 0.5f*(0.5f-x)*(0.5f-x); wz[1] = 0.75f - x*x; wz[2] = 0.5f*(0.5f+x)*(0.5f+x);
        int n = (int)nf;
        iz[0] = (n-1+4*NM)&(NM-1); iz[1] = (n+4*NM)&(NM-1); iz[2] = (n+1+4*NM)&(NM-1);
    }

    float acc0 = 0.f, acc1 = 0.f, acc2 = 0.f, acc3 = 0.f;
    #pragma unroll
    for (int dx = 0; dx < 3; ++dx) {
        int ox = ix[dx] * NM2;
        #pragma unroll
        for (int dy = 0; dy < 3; ++dy) {
            int oxy = ox + iy[dy] * NM;
            float wxy = wx[dx] * wy[dy];
            #pragma unroll
            for (int dz = 0; dz < 3; ++dz) {
                float w = wxy * wz[dz];
                float4 m = g_meshT[oxy + iz[dz]];
                acc0 += w * m.x; acc1 += w * m.y; acc2 += w * m.z; acc3 += w * m.w;
            }
        }
    }

    float wt = g_w2[g2];
    g_F[(p*A_CH + 0)*G_PAD + g2] = to_tf32(acc0 * wt);
    g_F[(p*A_CH + 1)*G_PAD + g2] = to_tf32(acc1 * wt);
    g_F[(p*A_CH + 2)*G_PAD + g2] = to_tf32(acc2 * wt);
    g_F[(p*A_CH + 3)*G_PAD + g2] = to_tf32(acc3 * wt);
}

// ---------------------------------------------------------------------------
// Kernel C: tf32 mma.sync GEMM.  C[m][kn] = sum_g F[m][g] * V2[kn][g]
// Block 128x64, BK=32, 8 warps (warp tile 32x32 = 2x4 m16n8k8), split-K 4,
// 3-stage cp.async ring (dynamic smem), single __syncthreads per iteration.
// ---------------------------------------------------------------------------
__global__ void __launch_bounds__(256, 1)
gemm_mma_kernel() {
    extern __shared__ float smem[];
    float* As = smem;                      // [3][BM][BKP]
    float* Bs = smem + 3 * A_STAGE_F;      // [3][BN][BKP]

    const int tid  = threadIdx.x;
    const int lane = tid & 31;
    const int wid  = tid >> 5;
    const int warpM = wid & 3;    // 4 warps over M (32 rows each)
    const int warpN = wid >> 2;   // 2 warps over N (32 cols each)
    const int gRow = lane >> 2;   // 0..7
    const int gCol = lane & 3;    // 0..3

    const int n0    = blockIdx.x * BN;
    const int m0    = blockIdx.y * BM;
    const int bz    = blockIdx.z;
    const int kbase = bz * KCHUNK;

    uint32_t asBase = (uint32_t)__cvta_generic_to_shared(As);
    uint32_t bsBase = (uint32_t)__cvta_generic_to_shared(Bs);

    // one stage: A = 1024 cp16 (4/thread), B = 512 cp16 (2/thread)
    auto load_stage = [&](int it, int buf) {
        int kofs = kbase + it * BK;
        #pragma unroll
        for (int i = 0; i < 4; ++i) {
            int e   = tid + i * 256;
            int row = e >> 3;          // 0..127
            int c4  = e & 7;           // 0..7 -> 4-float group
            uint32_t dst = asBase + (buf * A_STAGE_F + row * BKP + c4 * 4) * 4;
            const float* src = g_F + (size_t)(m0 + row) * G_PAD + kofs + c4 * 4;
            CP_ASYNC16(dst, src);
        }
        #pragma unroll
        for (int i = 0; i < 2; ++i) {
            int e   = tid + i * 256;
            int row = e >> 3;          // 0..63
            int c4  = e & 7;
            uint32_t dst = bsBase + (buf * B_STAGE_F + row * BKP + c4 * 4) * 4;
            const float* src = g_V2 + (size_t)(n0 + row) * G_PAD + kofs + c4 * 4;
            CP_ASYNC16(dst, src);
        }
        CP_COMMIT();
    };

    float c[2][4][4];
    #pragma unroll
    for (int mt = 0; mt < 2; ++mt)
        #pragma unroll
        for (int nt = 0; nt < 4; ++nt)
            #pragma unroll
            for (int j = 0; j < 4; ++j) c[mt][nt][j] = 0.f;

    load_stage(0, 0);
    load_stage(1, 1);

    #pragma unroll 1
    for (int it = 0; it < NIT; ++it) {
        int buf = it % 3;
        if (it == NIT - 1) { CP_WAIT(0); } else { CP_WAIT(1); }
        __syncthreads();
        if (it + 2 < NIT) load_stage(it + 2, (it + 2) % 3);

        const float* Ab = As + buf * A_STAGE_F;
        const float* Bb = Bs + buf * B_STAGE_F;

        #pragma unroll
        for (int ks = 0; ks < 4; ++ks) {
            uint32_t a[2][4], b[4][2];
            #pragma unroll
            for (int mt = 0; mt < 2; ++mt) {
                int r = warpM * 32 + mt * 16 + gRow;
                a[mt][0] = __float_as_uint(Ab[(r    ) * BKP + ks*8     + gCol]);
                a[mt][1] = __float_as_uint(Ab[(r + 8) * BKP + ks*8     + gCol]);
                a[mt][2] = __float_as_uint(Ab[(r    ) * BKP + ks*8 + 4 + gCol]);
                a[mt][3] = __float_as_uint(Ab[(r + 8) * BKP + ks*8 + 4 + gCol]);
            }
            #pragma unroll
            for (int nt = 0; nt < 4; ++nt) {
                int rb = warpN * 32 + nt * 8 + gRow;
                b[nt][0] = __float_as_uint(Bb[rb * BKP + ks*8     + gCol]);
                b[nt][1] = __float_as_uint(Bb[rb * BKP + ks*8 + 4 + gCol]);
            }
            #pragma unroll
            for (int mt = 0; mt < 2; ++mt)
                #pragma unroll
                for (int nt = 0; nt < 4; ++nt)
                    MMA_TF32(c[mt][nt], a[mt], b[nt]);
        }
    }

    // epilogue: partials, float2 stores
    #pragma unroll
    for (int mt = 0; mt < 2; ++mt) {
        int row = m0 + warpM * 32 + mt * 16 + gRow;
        #pragma unroll
        for (int nt = 0; nt < 4; ++nt) {
            int col = n0 + warpN * 32 + nt * 8 + gCol * 2;
            float* base0 = g_part + ((size_t)bz * M_ROWS + row)     * KN_PAD + col;
            float* base1 = g_part + ((size_t)bz * M_ROWS + row + 8) * KN_PAD + col;
            *reinterpret_cast<float2*>(base0) = make_float2(c[mt][nt][0], c[mt][nt][1]);
            *reinterpret_cast<float2*>(base1) = make_float2(c[mt][nt][2], c[mt][nt][3]);
        }
    }
}

// ---------------------------------------------------------------------------
// Kernel D: split-K reduce + pkan permutation (coalesced out writes)
// ---------------------------------------------------------------------------
__global__ void __launch_bounds__(256)
reduce_kernel(float* __restrict__ out) {
    int idx = blockIdx.x * blockDim.x + threadIdx.x;
    if (idx >= M_ROWS * KN_COLS) return;
    // out layout: ((p*49 + k)*4 + a)*8 + n
    int n   = idx & 7;
    int a   = (idx >> 3) & 3;
    int rem = idx >> 5;
    int k   = rem % K_DIM;
    int p   = rem / K_DIM;
    int m   = p * A_CH + a;
    int kn  = k * N_DIM + n;
    size_t o = (size_t)m * KN_PAD + kn;
    float s = 0.f;
    #pragma unroll
    for (int z = 0; z < KSPLIT; ++z)
        s += g_part[(size_t)z * M_ROWS * KN_PAD + o];
    out[idx] = s;
}

// ---------------------------------------------------------------------------
extern "C" void kernel_launch(void* const* d_in, const int* in_sizes, int n_in,
                              void* d_out, int out_size) {
    const float* positions = (const float*)d_in[0];
    const float* mesh      = (const float*)d_in[1];
    const float* cell      = (const float*)d_in[2];
    const float* values    = (const float*)d_in[3];
    const float* weights   = (const float*)d_in[4];
    const float* grid      = (const float*)d_in[5];
    float* out = (float*)d_out;
    (void)in_sizes; (void)n_in; (void)out_size;

    cudaFuncSetAttribute(gemm_mma_kernel,
                         cudaFuncAttributeMaxDynamicSharedMemorySize, SMEM_BYTES);

    prep_kernel<<<(NM3 + 255) / 256, 256>>>(mesh, values, weights, grid, cell);
    interp_kernel<<<(P_ATOMS * G_PTS + 255) / 256, 256>>>(positions);

    dim3 ggrid(KN_PAD / BN, M_ROWS / BM, KSPLIT);   // (7, 16, 4)
    gemm_mma_kernel<<<ggrid, 256, SMEM_BYTES>>>();

    reduce_kernel<<<(M_ROWS * KN_COLS + 255) / 256, 256>>>(out);
}

// round 7
// speedup vs baseline: 3.9414x; 1.1379x over previous
#include <cuda_runtime.h>
#include <cstdint>

// ---------------------------------------------------------------------------
// Problem constants
// ---------------------------------------------------------------------------
#define P_ATOMS 512
#define A_CH    4
#define K_DIM   49
#define N_DIM   8
#define NM      128
#define NM2     (NM*NM)
#define NM3     (NM*NM*NM)
#define G_PTS   1900
#define G_PAD   1920            // padded K (pad cols stay zero-init)
#define N_RAD   50
#define N_ANG   38
#define M_ROWS  (P_ATOMS*A_CH)  // 2048
#define KN_COLS (K_DIM*N_DIM)   // 392
#define KN_PAD  512             // padded N for GEMM tiles (4 * 128)

#define KSPLIT  2
#define KCHUNK  960             // 2*960 = 1920
#define BM      128
#define BN      128
#define BK      32
#define NIT     (KCHUNK/BK)     // 30
#define BKP     (BK + 4)        // padded row stride (36 floats)

#define A_STAGE_F (BM * BKP)            // 4608 floats
#define B_STAGE_F (BN * BKP)            // 4608 floats
#define SMEM_FLOATS (3 * (A_STAGE_F + B_STAGE_F))
#define SMEM_BYTES  (SMEM_FLOATS * 4)   // 110592 B

// ---------------------------------------------------------------------------
// Device scratch (zero-initialized at module load; pads never written)
// ---------------------------------------------------------------------------
__device__ float  g_F[M_ROWS * G_PAD];               // 15.7 MB
__device__ float  g_V2[KN_PAD * G_PAD];              // 3.9 MB
__device__ __align__(128) float4 g_meshT[NM3];       // 33.5 MB  Morton-2 blocks
__device__ float  g_w2[G_PTS];
__device__ float4 g_grid2[G_PTS];
__device__ float  g_part[KSPLIT * M_ROWS * KN_PAD];  // 8.4 MB
__device__ float  g_inv[9];                          // inverse cell (prep)

// ---------------------------------------------------------------------------
// helpers
// ---------------------------------------------------------------------------
__device__ __forceinline__ float to_tf32(float x) {
    uint32_t u;
    asm("cvt.rna.tf32.f32 %0, %1;" : "=r"(u) : "f"(x));
    return __uint_as_float(u);
}

#define CP_ASYNC16(dst, src) \
    asm volatile("cp.async.cg.shared.global [%0], [%1], 16;" :: "r"(dst), "l"(src) : "memory")
#define CP_COMMIT() asm volatile("cp.async.commit_group;" ::: "memory")
#define CP_WAIT(n)  asm volatile("cp.async.wait_group %0;" :: "n"(n) : "memory")

#define MMA_TF32(c, a, b) \
    asm volatile("mma.sync.aligned.m16n8k8.row.col.f32.tf32.tf32.f32 " \
        "{%0,%1,%2,%3}, {%4,%5,%6,%7}, {%8,%9}, {%0,%1,%2,%3};" \
        : "+f"((c)[0]), "+f"((c)[1]), "+f"((c)[2]), "+f"((c)[3]) \
        : "r"((a)[0]), "r"((a)[1]), "r"((a)[2]), "r"((a)[3]), \
          "r"((b)[0]), "r"((b)[1]))

// g2 = ang*50 + r   <->   g = r*38 + ang
__device__ __forceinline__ int g_from_g2(int g2) {
    int ang = g2 / N_RAD;
    int r   = g2 - ang * N_RAD;
    return r * N_ANG + ang;
}

// Morton-2 block layout: 2x2x2 cells per 128B line.
// idx = (((x>>1)*64 + (y>>1))*64 + (z>>1))*8 + (x&1)*4 + (y&1)*2 + (z&1)
__device__ __forceinline__ int morton2(int x, int y, int z) {
    return (((x >> 1) * 64 + (y >> 1)) * 64 + (z >> 1)) * 8
         + ((x & 1) << 2) + ((y & 1) << 1) + (z & 1);
}

// ---------------------------------------------------------------------------
// Kernel A: prep — mesh transpose (Morton-2, channel-last), g2-permutation,
// cell inverse
// ---------------------------------------------------------------------------
__global__ void __launch_bounds__(256)
prep_kernel(const float* __restrict__ mesh,
            const float* __restrict__ values,
            const float* __restrict__ weights,
            const float* __restrict__ grid,
            const float* __restrict__ cell) {
    int i = blockIdx.x * blockDim.x + threadIdx.x;
    if (i < NM3) {
        int z = i & (NM - 1);
        int y = (i >> 7) & (NM - 1);
        int x = i >> 14;
        float4 v;
        v.x = __ldg(mesh + i);
        v.y = __ldg(mesh + NM3 + i);
        v.z = __ldg(mesh + 2*NM3 + i);
        v.w = __ldg(mesh + 3*NM3 + i);
        g_meshT[morton2(x, y, z)] = v;
    }
    if (i < KN_COLS * G_PTS) {
        int row = i / G_PTS;
        int g2  = i - row * G_PTS;
        g_V2[row * G_PAD + g2] = to_tf32(__ldg(values + row * G_PTS + g_from_g2(g2)));
    }
    if (i < G_PTS) {
        int g = g_from_g2(i);
        g_w2[i] = __ldg(weights + g);
        float4 gp;
        gp.x = __ldg(grid + g*3 + 0);
        gp.y = __ldg(grid + g*3 + 1);
        gp.z = __ldg(grid + g*3 + 2);
        gp.w = 0.f;
        g_grid2[i] = gp;
    }
    if (i == 0) {
        float c00 = cell[0], c01 = cell[1], c02 = cell[2];
        float c10 = cell[3], c11 = cell[4], c12 = cell[5];
        float c20 = cell[6], c21 = cell[7], c22 = cell[8];
        float m00 = c11*c22 - c12*c21;
        float m01 = c02*c21 - c01*c22;
        float m02 = c01*c12 - c02*c11;
        float m10 = c12*c20 - c10*c22;
        float m11 = c00*c22 - c02*c20;
        float m12 = c02*c10 - c00*c12;
        float m20 = c10*c21 - c11*c20;
        float m21 = c01*c20 - c00*c21;
        float m22 = c00*c11 - c01*c10;
        float rdet = 1.0f / (c00*m00 + c01*m10 + c02*m20);
        g_inv[0] = m00*rdet; g_inv[1] = m01*rdet; g_inv[2] = m02*rdet;
        g_inv[3] = m10*rdet; g_inv[4] = m11*rdet; g_inv[5] = m12*rdet;
        g_inv[6] = m20*rdet; g_inv[7] = m21*rdet; g_inv[8] = m22*rdet;
    }
}

// ---------------------------------------------------------------------------
// Kernel B: B-spline interpolation -> tf32-rounded F[(p,a)][g2]
// Morton-2 mesh indices stay factorized: idx = xpart + ypart + zpart.
// ---------------------------------------------------------------------------
__global__ void __launch_bounds__(256)
interp_kernel(const float* __restrict__ pos) {
    int tid = blockIdx.x * blockDim.x + threadIdx.x;
    if (tid >= P_ATOMS * G_PTS) return;
    int p  = tid / G_PTS;
    int g2 = tid - p * G_PTS;

    float m00 = g_inv[0], m01 = g_inv[1], m02 = g_inv[2];
    float m10 = g_inv[3], m11 = g_inv[4], m12 = g_inv[5];
    float m20 = g_inv[6], m21 = g_inv[7], m22 = g_inv[8];

    float4 gp = g_grid2[g2];
    float px = __ldg(pos + p*3 + 0) + gp.x;
    float py = __ldg(pos + p*3 + 1) + gp.y;
    float pz = __ldg(pos + p*3 + 2) + gp.z;

    float fx = px*m00 + py*m10 + pz*m20;
    float fy = px*m01 + py*m11 + pz*m21;
    float fz = px*m02 + py*m12 + pz*m22;

    float wx[3], wy[3], wz[3];
    int xpart[3], ypart[3], zpart[3];
    {
        float u = fx * (float)NM, nf = floorf(u + 0.5f), x = u - nf;
        wx[0] = 0.5f*(0.5f-x)*(0.5f-x); wx[1] = 0.75f - x*x; wx[2] = 0.5f*(0.5f+x)*(0.5f+x);
        int n = (int)nf;
        #pragma unroll
        for (int d = 0; d < 3; ++d) {
            int v = (n + d - 1 + 4*NM) & (NM-1);
            xpart[d] = (v >> 1) * 32768 + (v & 1) * 4;
        }
    }
    {
        float u = fy * (float)NM, nf = floorf(u + 0.5f), x = u - nf;
        wy[0] = 0.5f*(0.5f-x)*(0.5f-x); wy[1] = 0.75f - x*x; wy[2] = 0.5f*(0.5f+x)*(0.5f+x);
        int n = (int)nf;
        #pragma unroll
        for (int d = 0; d < 3; ++d) {
            int v = (n + d - 1 + 4*NM) & (NM-1);
            ypart[d] = (v >> 1) * 512 + (v & 1) * 2;
        }
    }
    {
        float u = fz * (float)NM, nf = floorf(u + 0.5f), x = u - nf;
        wz[0] = 0.5f*(0.5f-x)*(0.5f-x); wz[1] = 0.75f - x*x; wz[2] = 0.5f*(0.5f+x)*(0.5f+x);
        int n = (int)nf;
        #pragma unroll
        for (int d = 0; d < 3; ++d) {
            int v = (n + d - 1 + 4*NM) & (NM-1);
            zpart[d] = (v >> 1) * 8 + (v & 1);
        }
    }

    float acc0 = 0.f, acc1 = 0.f, acc2 = 0.f, acc3 = 0.f;
    #pragma unroll
    for (int dx = 0; dx < 3; ++dx) {
        #pragma unroll
        for (int dy = 0; dy < 3; ++dy) {
            int oxy = xpart[dx] + ypart[dy];
            float wxy = wx[dx] * wy[dy];
            #pragma unroll
            for (int dz = 0; dz < 3; ++dz) {
                float w = wxy * wz[dz];
                float4 m = g_meshT[oxy + zpart[dz]];
                acc0 += w * m.x; acc1 += w * m.y; acc2 += w * m.z; acc3 += w * m.w;
            }
        }
    }

    float wt = g_w2[g2];
    g_F[(p*A_CH + 0)*G_PAD + g2] = to_tf32(acc0 * wt);
    g_F[(p*A_CH + 1)*G_PAD + g2] = to_tf32(acc1 * wt);
    g_F[(p*A_CH + 2)*G_PAD + g2] = to_tf32(acc2 * wt);
    g_F[(p*A_CH + 3)*G_PAD + g2] = to_tf32(acc3 * wt);
}

// ---------------------------------------------------------------------------
// Kernel C: tf32 mma.sync GEMM.  C[m][kn] = sum_g F[m][g] * V2[kn][g]
// Block 128x128, BK=32, 8 warps (warp tile 64x32 = 4x4 m16n8k8), split-K 2,
// grid (4,16,2) = 128 CTAs = one wave. 3-stage cp.async ring.
// ---------------------------------------------------------------------------
__global__ void __launch_bounds__(256, 1)
gemm_mma_kernel() {
    extern __shared__ float smem[];
    float* As = smem;                      // [3][BM][BKP]
    float* Bs = smem + 3 * A_STAGE_F;      // [3][BN][BKP]

    const int tid  = threadIdx.x;
    const int lane = tid & 31;
    const int wid  = tid >> 5;
    const int warpM = wid & 1;    // 2 warps over M (64 rows each)
    const int warpN = wid >> 1;   // 4 warps over N (32 cols each)
    const int gRow = lane >> 2;   // 0..7
    const int gCol = lane & 3;    // 0..3

    const int n0    = blockIdx.x * BN;
    const int m0    = blockIdx.y * BM;
    const int bz    = blockIdx.z;
    const int kbase = bz * KCHUNK;

    uint32_t asBase = (uint32_t)__cvta_generic_to_shared(As);
    uint32_t bsBase = (uint32_t)__cvta_generic_to_shared(Bs);

    // one stage: A = 1024 cp16 (4/thread), B = 1024 cp16 (4/thread)
    auto load_stage = [&](int it, int buf) {
        int kofs = kbase + it * BK;
        #pragma unroll
        for (int i = 0; i < 4; ++i) {
            int e   = tid + i * 256;
            int row = e >> 3;          // 0..127
            int c4  = e & 7;           // 0..7 -> 4-float group
            uint32_t dstA = asBase + (buf * A_STAGE_F + row * BKP + c4 * 4) * 4;
            const float* srcA = g_F + (size_t)(m0 + row) * G_PAD + kofs + c4 * 4;
            CP_ASYNC16(dstA, srcA);
            uint32_t dstB = bsBase + (buf * B_STAGE_F + row * BKP + c4 * 4) * 4;
            const float* srcB = g_V2 + (size_t)(n0 + row) * G_PAD + kofs + c4 * 4;
            CP_ASYNC16(dstB, srcB);
        }
        CP_COMMIT();
    };

    float c[4][4][4];
    #pragma unroll
    for (int mt = 0; mt < 4; ++mt)
        #pragma unroll
        for (int nt = 0; nt < 4; ++nt)
            #pragma unroll
            for (int j = 0; j < 4; ++j) c[mt][nt][j] = 0.f;

    load_stage(0, 0);
    load_stage(1, 1);

    #pragma unroll 1
    for (int it = 0; it < NIT; ++it) {
        int buf = it % 3;
        if (it == NIT - 1) { CP_WAIT(0); } else { CP_WAIT(1); }
        __syncthreads();
        if (it + 2 < NIT) load_stage(it + 2, (it + 2) % 3);

        const float* Ab = As + buf * A_STAGE_F;
        const float* Bb = Bs + buf * B_STAGE_F;

        #pragma unroll
        for (int ks = 0; ks < 4; ++ks) {
            uint32_t a[4][4], b[4][2];
            #pragma unroll
            for (int mt = 0; mt < 4; ++mt) {
                int r = warpM * 64 + mt * 16 + gRow;
                a[mt][0] = __float_as_uint(Ab[(r    ) * BKP + ks*8     + gCol]);
                a[mt][1] = __float_as_uint(Ab[(r + 8) * BKP + ks*8     + gCol]);
                a[mt][2] = __float_as_uint(Ab[(r    ) * BKP + ks*8 + 4 + gCol]);
                a[mt][3] = __float_as_uint(Ab[(r + 8) * BKP + ks*8 + 4 + gCol]);
            }
            #pragma unroll
            for (int nt = 0; nt < 4; ++nt) {
                int rb = warpN * 32 + nt * 8 + gRow;
                b[nt][0] = __float_as_uint(Bb[rb * BKP + ks*8     + gCol]);
                b[nt][1] = __float_as_uint(Bb[rb * BKP + ks*8 + 4 + gCol]);
            }
            #pragma unroll
            for (int mt = 0; mt < 4; ++mt)
                #pragma unroll
                for (int nt = 0; nt < 4; ++nt)
                    MMA_TF32(c[mt][nt], a[mt], b[nt]);
        }
    }

    // epilogue: partials, float2 stores
    #pragma unroll
    for (int mt = 0; mt < 4; ++mt) {
        int row = m0 + warpM * 64 + mt * 16 + gRow;
        #pragma unroll
        for (int nt = 0; nt < 4; ++nt) {
            int col = n0 + warpN * 32 + nt * 8 + gCol * 2;
            float* base0 = g_part + ((size_t)bz * M_ROWS + row)     * KN_PAD + col;
            float* base1 = g_part + ((size_t)bz * M_ROWS + row + 8) * KN_PAD + col;
            *reinterpret_cast<float2*>(base0) = make_float2(c[mt][nt][0], c[mt][nt][1]);
            *reinterpret_cast<float2*>(base1) = make_float2(c[mt][nt][2], c[mt][nt][3]);
        }
    }
}

// ---------------------------------------------------------------------------
// Kernel D: split-K reduce + pkan permutation (coalesced out writes)
// ---------------------------------------------------------------------------
__global__ void __launch_bounds__(256)
reduce_kernel(float* __restrict__ out) {
    int idx = blockIdx.x * blockDim.x + threadIdx.x;
    if (idx >= M_ROWS * KN_COLS) return;
    // out layout: ((p*49 + k)*4 + a)*8 + n
    int n   = idx & 7;
    int a   = (idx >> 3) & 3;
    int rem = idx >> 5;
    int k   = rem % K_DIM;
    int p   = rem / K_DIM;
    int m   = p * A_CH + a;
    int kn  = k * N_DIM + n;
    size_t o = (size_t)m * KN_PAD + kn;
    float s = 0.f;
    #pragma unroll
    for (int z = 0; z < KSPLIT; ++z)
        s += g_part[(size_t)z * M_ROWS * KN_PAD + o];
    out[idx] = s;
}

// ---------------------------------------------------------------------------
extern "C" void kernel_launch(void* const* d_in, const int* in_sizes, int n_in,
                              void* d_out, int out_size) {
    const float* positions = (const float*)d_in[0];
    const float* mesh      = (const float*)d_in[1];
    const float* cell      = (const float*)d_in[2];
    const float* values    = (const float*)d_in[3];
    const float* weights   = (const float*)d_in[4];
    const float* grid      = (const float*)d_in[5];
    float* out = (float*)d_out;
    (void)in_sizes; (void)n_in; (void)out_size;

    cudaFuncSetAttribute(gemm_mma_kernel,
                         cudaFuncAttributeMaxDynamicSharedMemorySize, SMEM_BYTES);

    prep_kernel<<<(NM3 + 255) / 256, 256>>>(mesh, values, weights, grid, cell);
    interp_kernel<<<(P_ATOMS * G_PTS + 255) / 256, 256>>>(positions);

    dim3 ggrid(KN_PAD / BN, M_ROWS / BM, KSPLIT);   // (4, 16, 2)
    gemm_mma_kernel<<<ggrid, 256, SMEM_BYTES>>>();

    reduce_kernel<<<(M_ROWS * KN_COLS + 255) / 256, 256>>>(out);
}

// round 8
// speedup vs baseline: 4.8088x; 1.2201x over previous
#include <cuda_runtime.h>
#include <cuda_fp16.h>
#include <cstdint>

// ---------------------------------------------------------------------------
// Problem constants
// ---------------------------------------------------------------------------
#define P_ATOMS 512
#define A_CH    4
#define K_DIM   49
#define N_DIM   8
#define NM      128
#define NM2     (NM*NM)
#define NM3     (NM*NM*NM)
#define G_PTS   1900
#define G_PAD   1920            // padded K (pad cols stay zero-init)
#define N_RAD   50
#define N_ANG   38
#define M_ROWS  (P_ATOMS*A_CH)  // 2048
#define KN_COLS (K_DIM*N_DIM)   // 392
#define KN_PAD  512             // padded N for GEMM tiles (4 * 128)

#define KSPLIT  2
#define KCHUNK  960             // 2*960 = 1920
#define BM      128
#define BN      128
#define BK      32
#define NIT     (KCHUNK/BK)     // 30
#define BKP     (BK + 4)        // padded row stride (36 floats)

#define A_STAGE_F (BM * BKP)            // 4608 floats
#define B_STAGE_F (BN * BKP)            // 4608 floats
#define SMEM_FLOATS (3 * (A_STAGE_F + B_STAGE_F))
#define SMEM_BYTES  (SMEM_FLOATS * 4)   // 110592 B

// ---------------------------------------------------------------------------
// Device scratch (zero-initialized at module load; pads never written)
// ---------------------------------------------------------------------------
__device__ float  g_F[M_ROWS * G_PAD];               // 15.7 MB
__device__ float  g_V2[KN_PAD * G_PAD];              // 3.9 MB
__device__ __align__(128) uint2 g_meshT[NM3];        // 16.8 MB  fp16x4, Morton-2
__device__ float  g_w2[G_PTS];
__device__ float4 g_grid2[G_PTS];
__device__ float  g_inv[9];                          // inverse cell (prep)

// ---------------------------------------------------------------------------
// helpers
// ---------------------------------------------------------------------------
__device__ __forceinline__ float to_tf32(float x) {
    uint32_t u;
    asm("cvt.rna.tf32.f32 %0, %1;" : "=r"(u) : "f"(x));
    return __uint_as_float(u);
}

#define CP_ASYNC16(dst, src) \
    asm volatile("cp.async.cg.shared.global [%0], [%1], 16;" :: "r"(dst), "l"(src) : "memory")
#define CP_COMMIT() asm volatile("cp.async.commit_group;" ::: "memory")
#define CP_WAIT(n)  asm volatile("cp.async.wait_group %0;" :: "n"(n) : "memory")

#define MMA_TF32(c, a, b) \
    asm volatile("mma.sync.aligned.m16n8k8.row.col.f32.tf32.tf32.f32 " \
        "{%0,%1,%2,%3}, {%4,%5,%6,%7}, {%8,%9}, {%0,%1,%2,%3};" \
        : "+f"((c)[0]), "+f"((c)[1]), "+f"((c)[2]), "+f"((c)[3]) \
        : "r"((a)[0]), "r"((a)[1]), "r"((a)[2]), "r"((a)[3]), \
          "r"((b)[0]), "r"((b)[1]))

// g2 = ang*50 + r   <->   g = r*38 + ang
__device__ __forceinline__ int g_from_g2(int g2) {
    int ang = g2 / N_RAD;
    int r   = g2 - ang * N_RAD;
    return r * N_ANG + ang;
}

// Morton-2 block layout: 2x2x2 cells (8 B each) per 64 B block.
__device__ __forceinline__ int morton2(int x, int y, int z) {
    return (((x >> 1) * 64 + (y >> 1)) * 64 + (z >> 1)) * 8
         + ((x & 1) << 2) + ((y & 1) << 1) + (z & 1);
}

// ---------------------------------------------------------------------------
// Kernel A: prep — mesh transpose (Morton-2, channel-last fp16), g2 perms,
// cell inverse
// ---------------------------------------------------------------------------
__global__ void __launch_bounds__(256)
prep_kernel(const float* __restrict__ mesh,
            const float* __restrict__ values,
            const float* __restrict__ weights,
            const float* __restrict__ grid,
            const float* __restrict__ cell) {
    int i = blockIdx.x * blockDim.x + threadIdx.x;
    if (i < NM3) {
        int z = i & (NM - 1);
        int y = (i >> 7) & (NM - 1);
        int x = i >> 14;
        __half2 h01 = __floats2half2_rn(__ldg(mesh + i),         __ldg(mesh + NM3 + i));
        __half2 h23 = __floats2half2_rn(__ldg(mesh + 2*NM3 + i), __ldg(mesh + 3*NM3 + i));
        uint2 v;
        v.x = *reinterpret_cast<uint32_t*>(&h01);
        v.y = *reinterpret_cast<uint32_t*>(&h23);
        g_meshT[morton2(x, y, z)] = v;
    }
    if (i < KN_COLS * G_PTS) {
        int row = i / G_PTS;
        int g2  = i - row * G_PTS;
        g_V2[row * G_PAD + g2] = to_tf32(__ldg(values + row * G_PTS + g_from_g2(g2)));
    }
    if (i < G_PTS) {
        int g = g_from_g2(i);
        g_w2[i] = __ldg(weights + g);
        float4 gp;
        gp.x = __ldg(grid + g*3 + 0);
        gp.y = __ldg(grid + g*3 + 1);
        gp.z = __ldg(grid + g*3 + 2);
        gp.w = 0.f;
        g_grid2[i] = gp;
    }
    if (i == 0) {
        float c00 = cell[0], c01 = cell[1], c02 = cell[2];
        float c10 = cell[3], c11 = cell[4], c12 = cell[5];
        float c20 = cell[6], c21 = cell[7], c22 = cell[8];
        float m00 = c11*c22 - c12*c21;
        float m01 = c02*c21 - c01*c22;
        float m02 = c01*c12 - c02*c11;
        float m10 = c12*c20 - c10*c22;
        float m11 = c00*c22 - c02*c20;
        float m12 = c02*c10 - c00*c12;
        float m20 = c10*c21 - c11*c20;
        float m21 = c01*c20 - c00*c21;
        float m22 = c00*c11 - c01*c10;
        float rdet = 1.0f / (c00*m00 + c01*m10 + c02*m20);
        g_inv[0] = m00*rdet; g_inv[1] = m01*rdet; g_inv[2] = m02*rdet;
        g_inv[3] = m10*rdet; g_inv[4] = m11*rdet; g_inv[5] = m12*rdet;
        g_inv[6] = m20*rdet; g_inv[7] = m21*rdet; g_inv[8] = m22*rdet;
    }
}

// ---------------------------------------------------------------------------
// Kernel B: B-spline interpolation -> tf32-rounded F[(p,a)][g2]
// fp16 mesh: 8 B per stencil point, Morton-2 factorized indexing.
// ---------------------------------------------------------------------------
__global__ void __launch_bounds__(256)
interp_kernel(const float* __restrict__ pos) {
    int tid = blockIdx.x * blockDim.x + threadIdx.x;
    if (tid >= P_ATOMS * G_PTS) return;
    int p  = tid / G_PTS;
    int g2 = tid - p * G_PTS;

    float m00 = g_inv[0], m01 = g_inv[1], m02 = g_inv[2];
    float m10 = g_inv[3], m11 = g_inv[4], m12 = g_inv[5];
    float m20 = g_inv[6], m21 = g_inv[7], m22 = g_inv[8];

    float4 gp = g_grid2[g2];
    float px = __ldg(pos + p*3 + 0) + gp.x;
    float py = __ldg(pos + p*3 + 1) + gp.y;
    float pz = __ldg(pos + p*3 + 2) + gp.z;

    float fx = px*m00 + py*m10 + pz*m20;
    float fy = px*m01 + py*m11 + pz*m21;
    float fz = px*m02 + py*m12 + pz*m22;

    float wx[3], wy[3], wz[3];
    int xpart[3], ypart[3], zpart[3];
    {
        float u = fx * (float)NM, nf = floorf(u + 0.5f), x = u - nf;
        wx[0] = 0.5f*(0.5f-x)*(0.5f-x); wx[1] = 0.75f - x*x; wx[2] = 0.5f*(0.5f+x)*(0.5f+x);
        int n = (int)nf;
        #pragma unroll
        for (int d = 0; d < 3; ++d) {
            int v = (n + d - 1 + 4*NM) & (NM-1);
            xpart[d] = (v >> 1) * 32768 + (v & 1) * 4;
        }
    }
    {
        float u = fy * (float)NM, nf = floorf(u + 0.5f), x = u - nf;
        wy[0] = 0.5f*(0.5f-x)*(0.5f-x); wy[1] = 0.75f - x*x; wy[2] = 0.5f*(0.5f+x)*(0.5f+x);
        int n = (int)nf;
        #pragma unroll
        for (int d = 0; d < 3; ++d) {
            int v = (n + d - 1 + 4*NM) & (NM-1);
            ypart[d] = (v >> 1) * 512 + (v & 1) * 2;
        }
    }
    {
        float u = fz * (float)NM, nf = floorf(u + 0.5f), x = u - nf;
        wz[0] = 0.5f*(0.5f-x)*(0.5f-x); wz[1] = 0.75f - x*x; wz[2] = 0.5f*(0.5f+x)*(0.5f+x);
        int n = (int)nf;
        #pragma unroll
        for (int d = 0; d < 3; ++d) {
            int v = (n + d - 1 + 4*NM) & (NM-1);
            zpart[d] = (v >> 1) * 8 + (v & 1);
        }
    }

    float acc0 = 0.f, acc1 = 0.f, acc2 = 0.f, acc3 = 0.f;
    #pragma unroll
    for (int dx = 0; dx < 3; ++dx) {
        #pragma unroll
        for (int dy = 0; dy < 3; ++dy) {
            int oxy = xpart[dx] + ypart[dy];
            float wxy = wx[dx] * wy[dy];
            #pragma unroll
            for (int dz = 0; dz < 3; ++dz) {
                float w = wxy * wz[dz];
                uint2 v = g_meshT[oxy + zpart[dz]];
                float2 f01 = __half22float2(*reinterpret_cast<__half2*>(&v.x));
                float2 f23 = __half22float2(*reinterpret_cast<__half2*>(&v.y));
                acc0 += w * f01.x; acc1 += w * f01.y;
                acc2 += w * f23.x; acc3 += w * f23.y;
            }
        }
    }

    float wt = g_w2[g2];
    g_F[(p*A_CH + 0)*G_PAD + g2] = to_tf32(acc0 * wt);
    g_F[(p*A_CH + 1)*G_PAD + g2] = to_tf32(acc1 * wt);
    g_F[(p*A_CH + 2)*G_PAD + g2] = to_tf32(acc2 * wt);
    g_F[(p*A_CH + 3)*G_PAD + g2] = to_tf32(acc3 * wt);
}

// ---------------------------------------------------------------------------
// Kernel C: tf32 mma.sync GEMM.  out[pkan] += sum_g F[m][g] * V2[kn][g]
// Block 128x128, BK=32, 8 warps (warp tile 64x32), split-K 2, one wave.
// Epilogue: atomicAdd directly into out (pre-zeroed), pkan permuted.
// ---------------------------------------------------------------------------
__global__ void __launch_bounds__(256, 1)
gemm_mma_kernel(float* __restrict__ out) {
    extern __shared__ float smem[];
    float* As = smem;                      // [3][BM][BKP]
    float* Bs = smem + 3 * A_STAGE_F;      // [3][BN][BKP]

    const int tid  = threadIdx.x;
    const int lane = tid & 31;
    const int wid  = tid >> 5;
    const int warpM = wid & 1;    // 2 warps over M (64 rows each)
    const int warpN = wid >> 1;   // 4 warps over N (32 cols each)
    const int gRow = lane >> 2;   // 0..7
    const int gCol = lane & 3;    // 0..3

    const int n0    = blockIdx.x * BN;
    const int m0    = blockIdx.y * BM;
    const int bz    = blockIdx.z;
    const int kbase = bz * KCHUNK;

    uint32_t asBase = (uint32_t)__cvta_generic_to_shared(As);
    uint32_t bsBase = (uint32_t)__cvta_generic_to_shared(Bs);

    auto load_stage = [&](int it, int buf) {
        int kofs = kbase + it * BK;
        #pragma unroll
        for (int i = 0; i < 4; ++i) {
            int e   = tid + i * 256;
            int row = e >> 3;
            int c4  = e & 7;
            uint32_t dstA = asBase + (buf * A_STAGE_F + row * BKP + c4 * 4) * 4;
            const float* srcA = g_F + (size_t)(m0 + row) * G_PAD + kofs + c4 * 4;
            CP_ASYNC16(dstA, srcA);
            uint32_t dstB = bsBase + (buf * B_STAGE_F + row * BKP + c4 * 4) * 4;
            const float* srcB = g_V2 + (size_t)(n0 + row) * G_PAD + kofs + c4 * 4;
            CP_ASYNC16(dstB, srcB);
        }
        CP_COMMIT();
    };

    float c[4][4][4];
    #pragma unroll
    for (int mt = 0; mt < 4; ++mt)
        #pragma unroll
        for (int nt = 0; nt < 4; ++nt)
            #pragma unroll
            for (int j = 0; j < 4; ++j) c[mt][nt][j] = 0.f;

    load_stage(0, 0);
    load_stage(1, 1);

    #pragma unroll 1
    for (int it = 0; it < NIT; ++it) {
        int buf = it % 3;
        if (it == NIT - 1) { CP_WAIT(0); } else { CP_WAIT(1); }
        __syncthreads();
        if (it + 2 < NIT) load_stage(it + 2, (it + 2) % 3);

        const float* Ab = As + buf * A_STAGE_F;
        const float* Bb = Bs + buf * B_STAGE_F;

        #pragma unroll
        for (int ks = 0; ks < 4; ++ks) {
            uint32_t a[4][4], b[4][2];
            #pragma unroll
            for (int mt = 0; mt < 4; ++mt) {
                int r = warpM * 64 + mt * 16 + gRow;
                a[mt][0] = __float_as_uint(Ab[(r    ) * BKP + ks*8     + gCol]);
                a[mt][1] = __float_as_uint(Ab[(r + 8) * BKP + ks*8     + gCol]);
                a[mt][2] = __float_as_uint(Ab[(r    ) * BKP + ks*8 + 4 + gCol]);
                a[mt][3] = __float_as_uint(Ab[(r + 8) * BKP + ks*8 + 4 + gCol]);
            }
            #pragma unroll
            for (int nt = 0; nt < 4; ++nt) {
                int rb = warpN * 32 + nt * 8 + gRow;
                b[nt][0] = __float_as_uint(Bb[rb * BKP + ks*8     + gCol]);
                b[nt][1] = __float_as_uint(Bb[rb * BKP + ks*8 + 4 + gCol]);
            }
            #pragma unroll
            for (int mt = 0; mt < 4; ++mt)
                #pragma unroll
                for (int nt = 0; nt < 4; ++nt)
                    MMA_TF32(c[mt][nt], a[mt], b[nt]);
        }
    }

    // epilogue: atomicAdd into out, pkan layout. col & col+1 are adjacent n's.
    #pragma unroll
    for (int mt = 0; mt < 4; ++mt) {
        int row0 = m0 + warpM * 64 + mt * 16 + gRow;
        #pragma unroll
        for (int nt = 0; nt < 4; ++nt) {
            int col = n0 + warpN * 32 + nt * 8 + gCol * 2;
            if (col < KN_COLS) {
                int k = col >> 3;
                int n = col & 7;
                {
                    int p = row0 >> 2, a = row0 & 3;
                    float* dst = out + ((p * K_DIM + k) * A_CH + a) * N_DIM + n;
                    atomicAdd(dst,     c[mt][nt][0]);
                    atomicAdd(dst + 1, c[mt][nt][1]);
                }
                {
                    int row1 = row0 + 8;
                    int p = row1 >> 2, a = row1 & 3;
                    float* dst = out + ((p * K_DIM + k) * A_CH + a) * N_DIM + n;
                    atomicAdd(dst,     c[mt][nt][2]);
                    atomicAdd(dst + 1, c[mt][nt][3]);
                }
            }
        }
    }
}

// ---------------------------------------------------------------------------
extern "C" void kernel_launch(void* const* d_in, const int* in_sizes, int n_in,
                              void* d_out, int out_size) {
    const float* positions = (const float*)d_in[0];
    const float* mesh      = (const float*)d_in[1];
    const float* cell      = (const float*)d_in[2];
    const float* values    = (const float*)d_in[3];
    const float* weights   = (const float*)d_in[4];
    const float* grid      = (const float*)d_in[5];
    float* out = (float*)d_out;
    (void)in_sizes; (void)n_in;

    cudaFuncSetAttribute(gemm_mma_kernel,
                         cudaFuncAttributeMaxDynamicSharedMemorySize, SMEM_BYTES);

    prep_kernel<<<(NM3 + 255) / 256, 256>>>(mesh, values, weights, grid, cell);
    interp_kernel<<<(P_ATOMS * G_PTS + 255) / 256, 256>>>(positions);

    cudaMemsetAsync(out, 0, (size_t)out_size * sizeof(float));

    dim3 ggrid(KN_PAD / BN, M_ROWS / BM, KSPLIT);   // (4, 16, 2)
    gemm_mma_kernel<<<ggrid, 256, SMEM_BYTES>>>(out);
}

// round 9
// speedup vs baseline: 6.2782x; 1.3056x over previous
#include <cuda_runtime.h>
#include <cuda_fp16.h>
#include <cstdint>

// ---------------------------------------------------------------------------
// Problem constants
// ---------------------------------------------------------------------------
#define P_ATOMS 512
#define A_CH    4
#define K_DIM   49
#define N_DIM   8
#define NM      128
#define NM2     (NM*NM)
#define NM3     (NM*NM*NM)
#define NB      64              // blocks per dim (Morton-2)
#define G_PTS   1900
#define G_PAD   1920            // padded K (pad cols stay zero-init)
#define N_RAD   50
#define N_ANG   38
#define M_ROWS  (P_ATOMS*A_CH)  // 2048
#define KN_COLS (K_DIM*N_DIM)   // 392
#define KN_PAD  512             // padded N for GEMM tiles (4 * 128)

#define KSPLIT  2
#define KCHUNK  960             // 2*960 = 1920
#define BM      128
#define BN      128
#define BK      32
#define NIT     (KCHUNK/BK)     // 30
#define BKPH    (BK + 8)        // padded row stride in halves (40 -> 80 B rows)

#define A_STAGE_H (BM * BKPH)           // 5120 halves (10240 B)
#define B_STAGE_H (BN * BKPH)           // 5120 halves
#define SMEM_BYTES (3 * (A_STAGE_H + B_STAGE_H) * 2)   // 61440 B

// ---------------------------------------------------------------------------
// Device scratch (zero-initialized at module load; pads never written)
// ---------------------------------------------------------------------------
__device__ __half g_Fh[M_ROWS * G_PAD];              // 7.9 MB
__device__ __half g_V2h[KN_PAD * G_PAD];             // 2.0 MB
__device__ __align__(128) uint2 g_meshT[NM3];        // 16.8 MB  fp16x4, Morton-2
__device__ float  g_w2[G_PTS];
__device__ float4 g_grid2[G_PTS];
__device__ float  g_inv[9];                          // inverse cell (prep)

// ---------------------------------------------------------------------------
// helpers
// ---------------------------------------------------------------------------
#define CP_ASYNC16(dst, src) \
    asm volatile("cp.async.cg.shared.global [%0], [%1], 16;" :: "r"(dst), "l"(src) : "memory")
#define CP_COMMIT() asm volatile("cp.async.commit_group;" ::: "memory")
#define CP_WAIT(n)  asm volatile("cp.async.wait_group %0;" :: "n"(n) : "memory")

#define MMA_F16(c, a, b) \
    asm volatile("mma.sync.aligned.m16n8k16.row.col.f32.f16.f16.f32 " \
        "{%0,%1,%2,%3}, {%4,%5,%6,%7}, {%8,%9}, {%0,%1,%2,%3};" \
        : "+f"((c)[0]), "+f"((c)[1]), "+f"((c)[2]), "+f"((c)[3]) \
        : "r"((a)[0]), "r"((a)[1]), "r"((a)[2]), "r"((a)[3]), \
          "r"((b)[0]), "r"((b)[1]))

__device__ __forceinline__ uint32_t pack_h2(float a, float b) {
    __half2 h = __floats2half2_rn(a, b);
    return *reinterpret_cast<uint32_t*>(&h);
}

// g2 = ang*50 + r   <->   g = r*38 + ang
__device__ __forceinline__ int g_from_g2(int g2) {
    int ang = g2 / N_RAD;
    int r   = g2 - ang * N_RAD;
    return r * N_ANG + ang;
}

// ---------------------------------------------------------------------------
// Kernel A: prep. Thread i < 64^3: one Morton block (2x2x2 cells) — float2
// reads (z-pairs) and a fully coalesced 64 B write. Plus V2 permute->fp16,
// weights/grid permute, cell inverse.
// ---------------------------------------------------------------------------
__global__ void __launch_bounds__(256)
prep_kernel(const float* __restrict__ mesh,
            const float* __restrict__ values,
            const float* __restrict__ weights,
            const float* __restrict__ grid,
            const float* __restrict__ cell) {
    int i = blockIdx.x * blockDim.x + threadIdx.x;
    if (i < NB*NB*NB) {
        int bz = i & 63, by = (i >> 6) & 63, bx = i >> 12;
        uint2 cells[8];
        #pragma unroll
        for (int jx = 0; jx < 2; ++jx) {
            #pragma unroll
            for (int jy = 0; jy < 2; ++jy) {
                int x = 2*bx + jx, y = 2*by + jy;
                const float* base = mesh + ((size_t)x * NM + y) * NM + 2*bz;
                float2 f0 = __ldg((const float2*)(base));
                float2 f1 = __ldg((const float2*)(base + NM3));
                float2 f2 = __ldg((const float2*)(base + 2*NM3));
                float2 f3 = __ldg((const float2*)(base + 3*NM3));
                int o = jx*4 + jy*2;
                cells[o    ] = make_uint2(pack_h2(f0.x, f1.x), pack_h2(f2.x, f3.x));
                cells[o + 1] = make_uint2(pack_h2(f0.y, f1.y), pack_h2(f2.y, f3.y));
            }
        }
        uint4* dst = reinterpret_cast<uint4*>(g_meshT + (size_t)i * 8);
        const uint4* src = reinterpret_cast<const uint4*>(cells);
        dst[0] = src[0]; dst[1] = src[1]; dst[2] = src[2]; dst[3] = src[3];
    }
    if (i < KN_COLS * G_PTS) {
        int row = i / G_PTS;
        int g2  = i - row * G_PTS;
        g_V2h[row * G_PAD + g2] = __float2half_rn(__ldg(values + row * G_PTS + g_from_g2(g2)));
    }
    if (i < G_PTS) {
        int g = g_from_g2(i);
        g_w2[i] = __ldg(weights + g);
        float4 gp;
        gp.x = __ldg(grid + g*3 + 0);
        gp.y = __ldg(grid + g*3 + 1);
        gp.z = __ldg(grid + g*3 + 2);
        gp.w = 0.f;
        g_grid2[i] = gp;
    }
    if (i == 0) {
        float c00 = cell[0], c01 = cell[1], c02 = cell[2];
        float c10 = cell[3], c11 = cell[4], c12 = cell[5];
        float c20 = cell[6], c21 = cell[7], c22 = cell[8];
        float m00 = c11*c22 - c12*c21;
        float m01 = c02*c21 - c01*c22;
        float m02 = c01*c12 - c02*c11;
        float m10 = c12*c20 - c10*c22;
        float m11 = c00*c22 - c02*c20;
        float m12 = c02*c10 - c00*c12;
        float m20 = c10*c21 - c11*c20;
        float m21 = c01*c20 - c00*c21;
        float m22 = c00*c11 - c01*c10;
        float rdet = 1.0f / (c00*m00 + c01*m10 + c02*m20);
        g_inv[0] = m00*rdet; g_inv[1] = m01*rdet; g_inv[2] = m02*rdet;
        g_inv[3] = m10*rdet; g_inv[4] = m11*rdet; g_inv[5] = m12*rdet;
        g_inv[6] = m20*rdet; g_inv[7] = m21*rdet; g_inv[8] = m22*rdet;
    }
}

// ---------------------------------------------------------------------------
// Kernel B: B-spline interpolation -> fp16 F[(p,a)][g2]
// z-pair merged loads: 9 xy-combos x 2 z-block LDG.128 = 18 loads/thread.
// ---------------------------------------------------------------------------
__global__ void __launch_bounds__(256)
interp_kernel(const float* __restrict__ pos) {
    int tid = blockIdx.x * blockDim.x + threadIdx.x;
    if (tid >= P_ATOMS * G_PTS) return;
    int p  = tid / G_PTS;
    int g2 = tid - p * G_PTS;

    float m00 = g_inv[0], m01 = g_inv[1], m02 = g_inv[2];
    float m10 = g_inv[3], m11 = g_inv[4], m12 = g_inv[5];
    float m20 = g_inv[6], m21 = g_inv[7], m22 = g_inv[8];

    float4 gp = g_grid2[g2];
    float px = __ldg(pos + p*3 + 0) + gp.x;
    float py = __ldg(pos + p*3 + 1) + gp.y;
    float pz = __ldg(pos + p*3 + 2) + gp.z;

    float fx = px*m00 + py*m10 + pz*m20;
    float fy = px*m01 + py*m11 + pz*m21;
    float fz = px*m02 + py*m12 + pz*m22;

    // x, y: 3 separate granule parts (uint4 units: 16B granules)
    float wx[3], wy[3];
    int xpart[3], ypart[3];
    {
        float u = fx * (float)NM, nf = floorf(u + 0.5f), x = u - nf;
        wx[0] = 0.5f*(0.5f-x)*(0.5f-x); wx[1] = 0.75f - x*x; wx[2] = 0.5f*(0.5f+x)*(0.5f+x);
        int n = (int)nf;
        #pragma unroll
        for (int d = 0; d < 3; ++d) {
            int v = (n + d - 1 + 4*NM) & (NM-1);
            xpart[d] = (v >> 1) * 16384 + (v & 1) * 2;
        }
    }
    {
        float u = fy * (float)NM, nf = floorf(u + 0.5f), x = u - nf;
        wy[0] = 0.5f*(0.5f-x)*(0.5f-x); wy[1] = 0.75f - x*x; wy[2] = 0.5f*(0.5f+x)*(0.5f+x);
        int n = (int)nf;
        #pragma unroll
        for (int d = 0; d < 3; ++d) {
            int v = (n + d - 1 + 4*NM) & (NM-1);
            ypart[d] = (v >> 1) * 256 + (v & 1);
        }
    }
    // z: 2 block loads, each covering a contiguous cell pair; weight pairs
    int zpart[2];
    float zwA[2], zwB[2];
    {
        float u = fz * (float)NM, nf = floorf(u + 0.5f), x = u - nf;
        float wz0 = 0.5f*(0.5f-x)*(0.5f-x);
        float wz1 = 0.75f - x*x;
        float wz2 = 0.5f*(0.5f+x)*(0.5f+x);
        int nn = (int)nf + 4*NM;              // positive
        int b_lo = ((nn - 1) & (NM-1)) >> 1;
        int b_hi = ((nn + 1) & (NM-1)) >> 1;
        zpart[0] = b_lo * 4;                  // uint4 units: block*8 granules /2
        zpart[1] = b_hi * 4;
        bool odd = (nn & 1) != 0;
        zwA[0] = odd ? wz0 : 0.f;
        zwB[0] = odd ? wz1 : wz0;
        zwA[1] = odd ? wz2 : wz1;
        zwB[1] = odd ? 0.f : wz2;
    }

    const uint4* mesh4 = reinterpret_cast<const uint4*>(g_meshT);

    float acc0 = 0.f, acc1 = 0.f, acc2 = 0.f, acc3 = 0.f;
    #pragma unroll
    for (int dx = 0; dx < 3; ++dx) {
        #pragma unroll
        for (int dy = 0; dy < 3; ++dy) {
            int oxy = xpart[dx] + ypart[dy];
            float wxy = wx[dx] * wy[dy];
            #pragma unroll
            for (int dz = 0; dz < 2; ++dz) {
                uint4 v = __ldg(mesh4 + oxy + zpart[dz]);
                float wA = wxy * zwA[dz];
                float wB = wxy * zwB[dz];
                // cell0 = (v.x: ch01, v.y: ch23), cell1 = (v.z, v.w)
                float2 a01 = __half22float2(*reinterpret_cast<__half2*>(&v.x));
                float2 a23 = __half22float2(*reinterpret_cast<__half2*>(&v.y));
                float2 b01 = __half22float2(*reinterpret_cast<__half2*>(&v.z));
                float2 b23 = __half22float2(*reinterpret_cast<__half2*>(&v.w));
                acc0 += wA * a01.x + wB * b01.x;
                acc1 += wA * a01.y + wB * b01.y;
                acc2 += wA * a23.x + wB * b23.x;
                acc3 += wA * a23.y + wB * b23.y;
            }
        }
    }

    float wt = g_w2[g2];
    g_Fh[(p*A_CH + 0)*G_PAD + g2] = __float2half_rn(acc0 * wt);
    g_Fh[(p*A_CH + 1)*G_PAD + g2] = __float2half_rn(acc1 * wt);
    g_Fh[(p*A_CH + 2)*G_PAD + g2] = __float2half_rn(acc2 * wt);
    g_Fh[(p*A_CH + 3)*G_PAD + g2] = __float2half_rn(acc3 * wt);
}

// ---------------------------------------------------------------------------
// Kernel C: fp16 mma.sync GEMM (f32 accum).  out[pkan] += sum_g F*V2
// Block 128x128, BK=32 (2 k16 steps), 8 warps (warp tile 64x32), split-K 2,
// one wave. 3-stage cp.async ring. atomicAdd epilogue into pre-zeroed out.
// ---------------------------------------------------------------------------
__global__ void __launch_bounds__(256, 1)
gemm_mma_kernel(float* __restrict__ out) {
    extern __shared__ __half smemh[];
    __half* As = smemh;                     // [3][BM][BKPH]
    __half* Bs = smemh + 3 * A_STAGE_H;     // [3][BN][BKPH]

    const int tid  = threadIdx.x;
    const int lane = tid & 31;
    const int wid  = tid >> 5;
    const int warpM = wid & 1;    // 2 warps over M (64 rows each)
    const int warpN = wid >> 1;   // 4 warps over N (32 cols each)
    const int gRow = lane >> 2;   // 0..7
    const int gCol = lane & 3;    // 0..3

    const int n0    = blockIdx.x * BN;
    const int m0    = blockIdx.y * BM;
    const int bz    = blockIdx.z;
    const int kbase = bz * KCHUNK;

    uint32_t asBase = (uint32_t)__cvta_generic_to_shared(As);
    uint32_t bsBase = (uint32_t)__cvta_generic_to_shared(Bs);

    // one stage: A 512 cp16 chunks (2/thread), B 512 (2/thread). Row = 64 B.
    auto load_stage = [&](int it, int buf) {
        int kofs = kbase + it * BK;
        #pragma unroll
        for (int i = 0; i < 2; ++i) {
            int e   = tid + i * 256;
            int row = e >> 2;          // 0..127
            int c8  = e & 3;           // 16B chunk (8 halves)
            uint32_t dstA = asBase + (buf * A_STAGE_H + row * BKPH) * 2 + c8 * 16;
            const __half* srcA = g_Fh + (size_t)(m0 + row) * G_PAD + kofs + c8 * 8;
            CP_ASYNC16(dstA, srcA);
            uint32_t dstB = bsBase + (buf * B_STAGE_H + row * BKPH) * 2 + c8 * 16;
            const __half* srcB = g_V2h + (size_t)(n0 + row) * G_PAD + kofs + c8 * 8;
            CP_ASYNC16(dstB, srcB);
        }
        CP_COMMIT();
    };

    float c[4][4][4];
    #pragma unroll
    for (int mt = 0; mt < 4; ++mt)
        #pragma unroll
        for (int nt = 0; nt < 4; ++nt)
            #pragma unroll
            for (int j = 0; j < 4; ++j) c[mt][nt][j] = 0.f;

    load_stage(0, 0);
    load_stage(1, 1);

    #pragma unroll 1
    for (int it = 0; it < NIT; ++it) {
        int buf = it % 3;
        if (it == NIT - 1) { CP_WAIT(0); } else { CP_WAIT(1); }
        __syncthreads();
        if (it + 2 < NIT) load_stage(it + 2, (it + 2) % 3);

        const __half* Ab = As + buf * A_STAGE_H;
        const __half* Bb = Bs + buf * B_STAGE_H;

        #pragma unroll
        for (int ks = 0; ks < 2; ++ks) {
            uint32_t a[4][4], b[4][2];
            #pragma unroll
            for (int mt = 0; mt < 4; ++mt) {
                int r = warpM * 64 + mt * 16 + gRow;
                const __half* pa0 = Ab + (r    ) * BKPH + ks*16 + 2*gCol;
                const __half* pa1 = Ab + (r + 8) * BKPH + ks*16 + 2*gCol;
                a[mt][0] = *reinterpret_cast<const uint32_t*>(pa0);
                a[mt][1] = *reinterpret_cast<const uint32_t*>(pa1);
                a[mt][2] = *reinterpret_cast<const uint32_t*>(pa0 + 8);
                a[mt][3] = *reinterpret_cast<const uint32_t*>(pa1 + 8);
            }
            #pragma unroll
            for (int nt = 0; nt < 4; ++nt) {
                int rb = warpN * 32 + nt * 8 + gRow;
                const __half* pb = Bb + rb * BKPH + ks*16 + 2*gCol;
                b[nt][0] = *reinterpret_cast<const uint32_t*>(pb);
                b[nt][1] = *reinterpret_cast<const uint32_t*>(pb + 8);
            }
            #pragma unroll
            for (int mt = 0; mt < 4; ++mt)
                #pragma unroll
                for (int nt = 0; nt < 4; ++nt)
                    MMA_F16(c[mt][nt], a[mt], b[nt]);
        }
    }

    // epilogue: atomicAdd into out, pkan layout
    #pragma unroll
    for (int mt = 0; mt < 4; ++mt) {
        int row0 = m0 + warpM * 64 + mt * 16 + gRow;
        #pragma unroll
        for (int nt = 0; nt < 4; ++nt) {
            int col = n0 + warpN * 32 + nt * 8 + gCol * 2;
            if (col < KN_COLS) {
                int k = col >> 3;
                int n = col & 7;
                {
                    int p = row0 >> 2, a = row0 & 3;
                    float* dst = out + ((p * K_DIM + k) * A_CH + a) * N_DIM + n;
                    atomicAdd(dst,     c[mt][nt][0]);
                    atomicAdd(dst + 1, c[mt][nt][1]);
                }
                {
                    int row1 = row0 + 8;
                    int p = row1 >> 2, a = row1 & 3;
                    float* dst = out + ((p * K_DIM + k) * A_CH + a) * N_DIM + n;
                    atomicAdd(dst,     c[mt][nt][2]);
                    atomicAdd(dst + 1, c[mt][nt][3]);
                }
            }
        }
    }
}

// ---------------------------------------------------------------------------
extern "C" void kernel_launch(void* const* d_in, const int* in_sizes, int n_in,
                              void* d_out, int out_size) {
    const float* positions = (const float*)d_in[0];
    const float* mesh      = (const float*)d_in[1];
    const float* cell      = (const float*)d_in[2];
    const float* values    = (const float*)d_in[3];
    const float* weights   = (const float*)d_in[4];
    const float* grid      = (const float*)d_in[5];
    float* out = (float*)d_out;
    (void)in_sizes; (void)n_in;

    cudaFuncSetAttribute(gemm_mma_kernel,
                         cudaFuncAttributeMaxDynamicSharedMemorySize, SMEM_BYTES);

    prep_kernel<<<(KN_COLS * G_PTS + 255) / 256, 256>>>(mesh, values, weights, grid, cell);
    interp_kernel<<<(P_ATOMS * G_PTS + 255) / 256, 256>>>(positions);

    cudaMemsetAsync(out, 0, (size_t)out_size * sizeof(float));

    dim3 ggrid(KN_PAD / BN, M_ROWS / BM, KSPLIT);   // (4, 16, 2)
    gemm_mma_kernel<<<ggrid, 256, SMEM_BYTES>>>(out);
}

// round 10
// speedup vs baseline: 6.3976x; 1.0190x over previous
#include <cuda_runtime.h>
#include <cuda_fp16.h>
#include <cstdint>

// ---------------------------------------------------------------------------
// Problem constants
// ---------------------------------------------------------------------------
#define P_ATOMS 512
#define A_CH    4
#define K_DIM   49
#define N_DIM   8
#define NM      128
#define NM2     (NM*NM)
#define NM3     (NM*NM*NM)
#define NB      64              // blocks per dim (Morton-2)
#define G_PTS   1900
#define G_PAD   1920
#define N_RAD   50
#define N_ANG   38
#define M_ROWS  (P_ATOMS*A_CH)  // 2048
#define KN_COLS (K_DIM*N_DIM)   // 392
#define KN_PAD  512             // 4 * 128

#define KSPLIT  2
#define KCHUNK  960             // 2*960 = 1920
#define BM      128
#define BN      128
#define BK      32
#define NIT     (KCHUNK/BK)     // 30
#define BKPH    (BK + 8)        // padded row stride in halves (40 -> 80 B rows)
#define NSTAGES 4

#define A_STAGE_H (BM * BKPH)           // 5120 halves
#define B_STAGE_H (BN * BKPH)           // 5120 halves
#define SMEM_BYTES (NSTAGES * (A_STAGE_H + B_STAGE_H) * 2)   // 81920 B

// ---------------------------------------------------------------------------
// Device scratch (zero-initialized at module load; pads never written)
// ---------------------------------------------------------------------------
__device__ __half g_Fh[M_ROWS * G_PAD];              // 7.9 MB
__device__ __half g_V2h[KN_PAD * G_PAD];             // 2.0 MB
__device__ __align__(128) uint2 g_meshT[NM3];        // 16.8 MB  fp16x4, Morton-2
__device__ float  g_w2[G_PTS];
__device__ float4 g_grid2[G_PTS];
__device__ float  g_inv[9];

// ---------------------------------------------------------------------------
// helpers
// ---------------------------------------------------------------------------
#define CP_ASYNC16(dst, src) \
    asm volatile("cp.async.cg.shared.global [%0], [%1], 16;" :: "r"(dst), "l"(src) : "memory")
#define CP_COMMIT() asm volatile("cp.async.commit_group;" ::: "memory")
#define CP_WAIT(n)  asm volatile("cp.async.wait_group %0;" :: "n"(n) : "memory")

#define MMA_F16(c, a, b) \
    asm volatile("mma.sync.aligned.m16n8k16.row.col.f32.f16.f16.f32 " \
        "{%0,%1,%2,%3}, {%4,%5,%6,%7}, {%8,%9}, {%0,%1,%2,%3};" \
        : "+f"((c)[0]), "+f"((c)[1]), "+f"((c)[2]), "+f"((c)[3]) \
        : "r"((a)[0]), "r"((a)[1]), "r"((a)[2]), "r"((a)[3]), \
          "r"((b)[0]), "r"((b)[1]))

#define LDSM_X4(r0, r1, r2, r3, addr) \
    asm volatile("ldmatrix.sync.aligned.m8n8.x4.shared.b16 {%0,%1,%2,%3}, [%4];" \
        : "=r"(r0), "=r"(r1), "=r"(r2), "=r"(r3) : "r"(addr))

__device__ __forceinline__ uint32_t pack_h2(float a, float b) {
    __half2 h = __floats2half2_rn(a, b);
    return *reinterpret_cast<uint32_t*>(&h);
}

// g2 = ang*50 + r   <->   g = r*38 + ang
__device__ __forceinline__ int g_from_g2(int g2) {
    int ang = g2 / N_RAD;
    int r   = g2 - ang * N_RAD;
    return r * N_ANG + ang;
}

// ---------------------------------------------------------------------------
// Kernel A: prep (Morton block transpose -> fp16, V2 permute, grid/weights,
// cell inverse)
// ---------------------------------------------------------------------------
__global__ void __launch_bounds__(256)
prep_kernel(const float* __restrict__ mesh,
            const float* __restrict__ values,
            const float* __restrict__ weights,
            const float* __restrict__ grid,
            const float* __restrict__ cell) {
    int i = blockIdx.x * blockDim.x + threadIdx.x;
    if (i < NB*NB*NB) {
        int bz = i & 63, by = (i >> 6) & 63, bx = i >> 12;
        uint2 cells[8];
        #pragma unroll
        for (int jx = 0; jx < 2; ++jx) {
            #pragma unroll
            for (int jy = 0; jy < 2; ++jy) {
                int x = 2*bx + jx, y = 2*by + jy;
                const float* base = mesh + ((size_t)x * NM + y) * NM + 2*bz;
                float2 f0 = __ldg((const float2*)(base));
                float2 f1 = __ldg((const float2*)(base + NM3));
                float2 f2 = __ldg((const float2*)(base + 2*NM3));
                float2 f3 = __ldg((const float2*)(base + 3*NM3));
                int o = jx*4 + jy*2;
                cells[o    ] = make_uint2(pack_h2(f0.x, f1.x), pack_h2(f2.x, f3.x));
                cells[o + 1] = make_uint2(pack_h2(f0.y, f1.y), pack_h2(f2.y, f3.y));
            }
        }
        uint4* dst = reinterpret_cast<uint4*>(g_meshT + (size_t)i * 8);
        const uint4* src = reinterpret_cast<const uint4*>(cells);
        dst[0] = src[0]; dst[1] = src[1]; dst[2] = src[2]; dst[3] = src[3];
    }
    if (i < KN_COLS * G_PTS) {
        int row = i / G_PTS;
        int g2  = i - row * G_PTS;
        g_V2h[row * G_PAD + g2] = __float2half_rn(__ldg(values + row * G_PTS + g_from_g2(g2)));
    }
    if (i < G_PTS) {
        int g = g_from_g2(i);
        g_w2[i] = __ldg(weights + g);
        float4 gp;
        gp.x = __ldg(grid + g*3 + 0);
        gp.y = __ldg(grid + g*3 + 1);
        gp.z = __ldg(grid + g*3 + 2);
        gp.w = 0.f;
        g_grid2[i] = gp;
    }
    if (i == 0) {
        float c00 = cell[0], c01 = cell[1], c02 = cell[2];
        float c10 = cell[3], c11 = cell[4], c12 = cell[5];
        float c20 = cell[6], c21 = cell[7], c22 = cell[8];
        float m00 = c11*c22 - c12*c21;
        float m01 = c02*c21 - c01*c22;
        float m02 = c01*c12 - c02*c11;
        float m10 = c12*c20 - c10*c22;
        float m11 = c00*c22 - c02*c20;
        float m12 = c02*c10 - c00*c12;
        float m20 = c10*c21 - c11*c20;
        float m21 = c01*c20 - c00*c21;
        float m22 = c00*c11 - c01*c10;
        float rdet = 1.0f / (c00*m00 + c01*m10 + c02*m20);
        g_inv[0] = m00*rdet; g_inv[1] = m01*rdet; g_inv[2] = m02*rdet;
        g_inv[3] = m10*rdet; g_inv[4] = m11*rdet; g_inv[5] = m12*rdet;
        g_inv[6] = m20*rdet; g_inv[7] = m21*rdet; g_inv[8] = m22*rdet;
    }
}

// ---------------------------------------------------------------------------
// Kernel B: B-spline interpolation -> fp16 F[(p,a)][g2]
// 18 LDG.128 issued as one batch (MLP=18), then the FMA tree.
// ---------------------------------------------------------------------------
__global__ void __launch_bounds__(256)
interp_kernel(const float* __restrict__ pos) {
    int tid = blockIdx.x * blockDim.x + threadIdx.x;
    if (tid >= P_ATOMS * G_PTS) return;
    int p  = tid / G_PTS;
    int g2 = tid - p * G_PTS;

    float m00 = g_inv[0], m01 = g_inv[1], m02 = g_inv[2];
    float m10 = g_inv[3], m11 = g_inv[4], m12 = g_inv[5];
    float m20 = g_inv[6], m21 = g_inv[7], m22 = g_inv[8];

    float4 gp = g_grid2[g2];
    float px = __ldg(pos + p*3 + 0) + gp.x;
    float py = __ldg(pos + p*3 + 1) + gp.y;
    float pz = __ldg(pos + p*3 + 2) + gp.z;

    float fx = px*m00 + py*m10 + pz*m20;
    float fy = px*m01 + py*m11 + pz*m21;
    float fz = px*m02 + py*m12 + pz*m22;

    float wx[3], wy[3];
    int xpart[3], ypart[3];
    {
        float u = fx * (float)NM, nf = floorf(u + 0.5f), x = u - nf;
        wx[0] = 0.5f*(0.5f-x)*(0.5f-x); wx[1] = 0.75f - x*x; wx[2] = 0.5f*(0.5f+x)*(0.5f+x);
        int n = (int)nf;
        #pragma unroll
        for (int d = 0; d < 3; ++d) {
            int v = (n + d - 1 + 4*NM) & (NM-1);
            xpart[d] = (v >> 1) * 16384 + (v & 1) * 2;
        }
    }
    {
        float u = fy * (float)NM, nf = floorf(u + 0.5f), x = u - nf;
        wy[0] = 0.5f*(0.5f-x)*(0.5f-x); wy[1] = 0.75f - x*x; wy[2] = 0.5f*(0.5f+x)*(0.5f+x);
        int n = (int)nf;
        #pragma unroll
        for (int d = 0; d < 3; ++d) {
            int v = (n + d - 1 + 4*NM) & (NM-1);
            ypart[d] = (v >> 1) * 256 + (v & 1);
        }
    }
    int zpart[2];
    float zwA[2], zwB[2];
    {
        float u = fz * (float)NM, nf = floorf(u + 0.5f), x = u - nf;
        float wz0 = 0.5f*(0.5f-x)*(0.5f-x);
        float wz1 = 0.75f - x*x;
        float wz2 = 0.5f*(0.5f+x)*(0.5f+x);
        int nn = (int)nf + 4*NM;
        int b_lo = ((nn - 1) & (NM-1)) >> 1;
        int b_hi = ((nn + 1) & (NM-1)) >> 1;
        zpart[0] = b_lo * 4;
        zpart[1] = b_hi * 4;
        bool odd = (nn & 1) != 0;
        zwA[0] = odd ? wz0 : 0.f;
        zwB[0] = odd ? wz1 : wz0;
        zwA[1] = odd ? wz2 : wz1;
        zwB[1] = odd ? 0.f : wz2;
    }

    const uint4* mesh4 = reinterpret_cast<const uint4*>(g_meshT);

    // batch all 18 loads first (max MLP)
    uint4 v[18];
    #pragma unroll
    for (int dx = 0; dx < 3; ++dx)
        #pragma unroll
        for (int dy = 0; dy < 3; ++dy)
            #pragma unroll
            for (int dz = 0; dz < 2; ++dz)
                v[(dx*3 + dy)*2 + dz] = __ldg(mesh4 + xpart[dx] + ypart[dy] + zpart[dz]);

    float acc0 = 0.f, acc1 = 0.f, acc2 = 0.f, acc3 = 0.f;
    #pragma unroll
    for (int dx = 0; dx < 3; ++dx) {
        #pragma unroll
        for (int dy = 0; dy < 3; ++dy) {
            float wxy = wx[dx] * wy[dy];
            #pragma unroll
            for (int dz = 0; dz < 2; ++dz) {
                uint4 q = v[(dx*3 + dy)*2 + dz];
                float wA = wxy * zwA[dz];
                float wB = wxy * zwB[dz];
                float2 a01 = __half22float2(*reinterpret_cast<__half2*>(&q.x));
                float2 a23 = __half22float2(*reinterpret_cast<__half2*>(&q.y));
                float2 b01 = __half22float2(*reinterpret_cast<__half2*>(&q.z));
                float2 b23 = __half22float2(*reinterpret_cast<__half2*>(&q.w));
                acc0 += wA * a01.x + wB * b01.x;
                acc1 += wA * a01.y + wB * b01.y;
                acc2 += wA * a23.x + wB * b23.x;
                acc3 += wA * a23.y + wB * b23.y;
            }
        }
    }

    float wt = g_w2[g2];
    g_Fh[(p*A_CH + 0)*G_PAD + g2] = __float2half_rn(acc0 * wt);
    g_Fh[(p*A_CH + 1)*G_PAD + g2] = __float2half_rn(acc1 * wt);
    g_Fh[(p*A_CH + 2)*G_PAD + g2] = __float2half_rn(acc2 * wt);
    g_Fh[(p*A_CH + 3)*G_PAD + g2] = __float2half_rn(acc3 * wt);
}

// ---------------------------------------------------------------------------
// Kernel C: fp16 mma.sync GEMM with ldmatrix fragments, 4-stage cp.async.
// Block 128x128, BK=32, 8 warps (warp tile 64x32), split-K 2, one wave.
// ---------------------------------------------------------------------------
__global__ void __launch_bounds__(256, 1)
gemm_mma_kernel(float* __restrict__ out) {
    extern __shared__ __half smemh[];
    __half* As = smemh;                          // [4][BM][BKPH]
    __half* Bs = smemh + NSTAGES * A_STAGE_H;    // [4][BN][BKPH]

    const int tid  = threadIdx.x;
    const int lane = tid & 31;
    const int wid  = tid >> 5;
    const int warpM = wid & 1;
    const int warpN = wid >> 1;
    const int gRow = lane >> 2;
    const int gCol = lane & 3;

    const int n0    = blockIdx.x * BN;
    const int m0    = blockIdx.y * BM;
    const int bz    = blockIdx.z;
    const int kbase = bz * KCHUNK;

    uint32_t asBase = (uint32_t)__cvta_generic_to_shared(As);
    uint32_t bsBase = (uint32_t)__cvta_generic_to_shared(Bs);

    // ldmatrix lane-local address components (in halves)
    // A matrices j: row = (j&1)*8 + (lane&7), koff = (j>>1)*8
    const int rowA_l = (lane & 7) + (((lane >> 3) & 1) << 3);
    const int kA_l   = (lane >> 4) << 3;
    // B matrices j: row(n) = (j>>1)*8 + (lane&7), koff = (j&1)*8
    const int rowB_l = (lane & 7) + ((lane >> 4) << 3);
    const int kB_l   = ((lane >> 3) & 1) << 3;

    auto load_stage = [&](int it, int buf) {
        int kofs = kbase + it * BK;
        #pragma unroll
        for (int i = 0; i < 2; ++i) {
            int e   = tid + i * 256;
            int row = e >> 2;
            int c8  = e & 3;
            uint32_t dstA = asBase + (buf * A_STAGE_H + row * BKPH) * 2 + c8 * 16;
            const __half* srcA = g_Fh + (size_t)(m0 + row) * G_PAD + kofs + c8 * 8;
            CP_ASYNC16(dstA, srcA);
            uint32_t dstB = bsBase + (buf * B_STAGE_H + row * BKPH) * 2 + c8 * 16;
            const __half* srcB = g_V2h + (size_t)(n0 + row) * G_PAD + kofs + c8 * 8;
            CP_ASYNC16(dstB, srcB);
        }
        CP_COMMIT();
    };

    float c[4][4][4];
    #pragma unroll
    for (int mt = 0; mt < 4; ++mt)
        #pragma unroll
        for (int nt = 0; nt < 4; ++nt)
            #pragma unroll
            for (int j = 0; j < 4; ++j) c[mt][nt][j] = 0.f;

    load_stage(0, 0);
    load_stage(1, 1);
    load_stage(2, 2);

    #pragma unroll 1
    for (int it = 0; it < NIT; ++it) {
        int buf = it % NSTAGES;
        if (it <= NIT - 3)      { CP_WAIT(2); }
        else if (it == NIT - 2) { CP_WAIT(1); }
        else                    { CP_WAIT(0); }
        __syncthreads();
        if (it + 3 < NIT) load_stage(it + 3, (it + 3) % NSTAGES);

        uint32_t aBufBase = asBase + (buf * A_STAGE_H) * 2;
        uint32_t bBufBase = bsBase + (buf * B_STAGE_H) * 2;

        #pragma unroll
        for (int ks = 0; ks < 2; ++ks) {
            uint32_t a[4][4], b[4][2];
            #pragma unroll
            for (int mt = 0; mt < 4; ++mt) {
                int r = warpM * 64 + mt * 16 + rowA_l;
                uint32_t addr = aBufBase + (r * BKPH + ks * 16 + kA_l) * 2;
                LDSM_X4(a[mt][0], a[mt][1], a[mt][2], a[mt][3], addr);
            }
            #pragma unroll
            for (int pr = 0; pr < 2; ++pr) {       // nt pairs (0,1) and (2,3)
                int rb = warpN * 32 + pr * 16 + rowB_l;
                uint32_t addr = bBufBase + (rb * BKPH + ks * 16 + kB_l) * 2;
                LDSM_X4(b[2*pr][0], b[2*pr][1], b[2*pr+1][0], b[2*pr+1][1], addr);
            }
            #pragma unroll
            for (int mt = 0; mt < 4; ++mt)
                #pragma unroll
                for (int nt = 0; nt < 4; ++nt)
                    MMA_F16(c[mt][nt], a[mt], b[nt]);
        }
    }

    // epilogue: atomicAdd into out, pkan layout
    #pragma unroll
    for (int mt = 0; mt < 4; ++mt) {
        int row0 = m0 + warpM * 64 + mt * 16 + gRow;
        #pragma unroll
        for (int nt = 0; nt < 4; ++nt) {
            int col = n0 + warpN * 32 + nt * 8 + gCol * 2;
            if (col < KN_COLS) {
                int k = col >> 3;
                int n = col & 7;
                {
                    int p = row0 >> 2, a = row0 & 3;
                    float* dst = out + ((p * K_DIM + k) * A_CH + a) * N_DIM + n;
                    atomicAdd(dst,     c[mt][nt][0]);
                    atomicAdd(dst + 1, c[mt][nt][1]);
                }
                {
                    int row1 = row0 + 8;
                    int p = row1 >> 2, a = row1 & 3;
                    float* dst = out + ((p * K_DIM + k) * A_CH + a) * N_DIM + n;
                    atomicAdd(dst,     c[mt][nt][2]);
                    atomicAdd(dst + 1, c[mt][nt][3]);
                }
            }
        }
    }
}

// ---------------------------------------------------------------------------
extern "C" void kernel_launch(void* const* d_in, const int* in_sizes, int n_in,
                              void* d_out, int out_size) {
    const float* positions = (const float*)d_in[0];
    const float* mesh      = (const float*)d_in[1];
    const float* cell      = (const float*)d_in[2];
    const float* values    = (const float*)d_in[3];
    const float* weights   = (const float*)d_in[4];
    const float* grid      = (const float*)d_in[5];
    float* out = (float*)d_out;
    (void)in_sizes; (void)n_in;

    cudaFuncSetAttribute(gemm_mma_kernel,
                         cudaFuncAttributeMaxDynamicSharedMemorySize, SMEM_BYTES);

    prep_kernel<<<(KN_COLS * G_PTS + 255) / 256, 256>>>(mesh, values, weights, grid, cell);
    interp_kernel<<<(P_ATOMS * G_PTS + 255) / 256, 256>>>(positions);

    cudaMemsetAsync(out, 0, (size_t)out_size * sizeof(float));

    dim3 ggrid(KN_PAD / BN, M_ROWS / BM, KSPLIT);   // (4, 16, 2)
    gemm_mma_kernel<<<ggrid, 256, SMEM_BYTES>>>(out);
}